// round 11
// baseline (speedup 1.0000x reference)
#include <cuda_runtime.h>
#include <cuda_bf16.h>

// Shapes (compile-time; problem is fixed-shape)
#define B_   2
#define N_   1024
#define D_   256
#define E_   64
#define H_   8
#define HS_  64
#define FF_  1024
#define R_   (B_*N_)        // 2048 token rows
#define QKV_ (3*H_*HS_)     // 1536

// ---------------------------------------------------------------------------
// Scratch (device globals; no runtime allocation allowed)
// ---------------------------------------------------------------------------
__device__ float g_qkv[R_*QKV_];                    // q | kn | v   (12 MB)
__device__ float g_qe[R_*H_*E_];                    // 4 MB
__device__ float g_logits[(long)B_*H_*N_*N_];       // 64 MB (reused as attn probs)
__device__ float g_mo[R_*H_*HS_];                   // 4 MB
__device__ float g_mha[R_*D_];                      // 2 MB
__device__ float g_x[R_*D_];                        // 2 MB
__device__ float g_ffh[R_*FF_];                     // 8 MB
__device__ float g_ff[R_*D_];                       // 2 MB
__device__ float g_wqkvT[QKV_*D_];                  // [1536][256]
__device__ float g_WpT[D_*H_*HS_];                  // [256][512]
__device__ float g_W1T[FF_*D_];                     // [1024][256]
__device__ float g_W2T[D_*FF_];                     // [256][1024]
__device__ float g_vT[(long)B_*H_*HS_*N_];          // [b][h*64+o][m]  4 MB
__device__ float g_part[2*R_*QKV_];                 // 25 MB split-K partials

// ---------------------------------------------------------------------------
// Repack Wq (scaled by 1/sqrt(HS)), Wk[:, :D], Wv into TRANSPOSED [1536][256]
// ---------------------------------------------------------------------------
__global__ void repack_wqkvT(const float* __restrict__ Wq,
                             const float* __restrict__ Wk,
                             const float* __restrict__ Wv,
                             float* __restrict__ out)
{
    int idx = blockIdx.x * blockDim.x + threadIdx.x;   // idx = j*256 + i
    if (idx >= D_ * QKV_) return;
    int j = idx / D_;        // output column of fused proj (0..1535)
    int i = idx % D_;        // input feature (0..255)
    float v;
    if (j < 512) {
        int h = j >> 6, o = j & 63;
        v = Wq[(h*D_ + i)*HS_ + o] * 0.125f;               // 1/sqrt(64)
    } else if (j < 1024) {
        int jj = j - 512; int h = jj >> 6, o = jj & 63;
        v = Wk[(h*(D_+E_) + i)*HS_ + o];
    } else {
        int jj = j - 1024; int h = jj >> 6, o = jj & 63;
        v = Wv[(h*D_ + i)*HS_ + o];
    }
    out[idx] = v;
}

// ---------------------------------------------------------------------------
// Generic tiled transpose: in[Rr][Cc] -> out[Cc][Rr]. Rr, Cc multiples of 32.
// ---------------------------------------------------------------------------
__global__ void transpose_k(const float* __restrict__ in, float* __restrict__ out,
                            int Rr, int Cc)
{
    __shared__ float tile[32][33];
    int x = blockIdx.x*32 + threadIdx.x;
    int y0 = blockIdx.y*32;
#pragma unroll
    for (int j = 0; j < 32; j += 8)
        tile[threadIdx.y + j][threadIdx.x] = in[(long)(y0 + threadIdx.y + j)*Cc + x];
    __syncthreads();
    int ox = y0 + threadIdx.x;
    int oy0 = blockIdx.x*32;
#pragma unroll
    for (int j = 0; j < 32; j += 8)
        out[(long)(oy0 + threadIdx.y + j)*Rr + ox] = tile[threadIdx.x][threadIdx.y + j];
}

// ---------------------------------------------------------------------------
// vT[b][c][m] = qkv[b*1024 + m][1024 + c]   (c = h*64+o, m = token)
// ---------------------------------------------------------------------------
__global__ void vt_kernel(const float* __restrict__ qkv, float* __restrict__ vT)
{
    __shared__ float tile[32][33];
    int b  = blockIdx.z;
    int c0 = blockIdx.x*32;
    int m0 = blockIdx.y*32;
#pragma unroll
    for (int j = 0; j < 32; j += 8)
        tile[threadIdx.y + j][threadIdx.x] =
            qkv[(long)(b*N_ + m0 + threadIdx.y + j)*QKV_ + 1024 + c0 + threadIdx.x];
    __syncthreads();
#pragma unroll
    for (int j = 0; j < 32; j += 8)
        vT[(long)(b*512 + c0 + threadIdx.y + j)*N_ + m0 + threadIdx.x] =
            tile[threadIdx.x][threadIdx.y + j];
}

// ---------------------------------------------------------------------------
// Deterministic slab reduction: out[i] = sum_j part[i + j*slab4] (float4 units)
// ---------------------------------------------------------------------------
__global__ void reduce_add(const float* __restrict__ part, float* __restrict__ out,
                           int n4, int nslab, long slab4)
{
    int i = blockIdx.x * blockDim.x + threadIdx.x;
    if (i >= n4) return;
    const float4* pp = (const float4*)part;
    float4 s = pp[i];
    for (int j = 1; j < nslab; ++j) {
        float4 v = pp[i + (long)j*slab4];
        s.x += v.x; s.y += v.y; s.z += v.z; s.w += v.w;
    }
    ((float4*)out)[i] = s;
}

// ---------------------------------------------------------------------------
// bf16 helpers / PTX wrappers
// ---------------------------------------------------------------------------
__device__ __forceinline__ void split_bf16(float v, __nv_bfloat16& h, __nv_bfloat16& l)
{
    h = __float2bfloat16(v);
    l = __float2bfloat16(v - __bfloat162float(h));
}

__device__ __forceinline__ unsigned smem_addr_u32(const void* p)
{
    return (unsigned)__cvta_generic_to_shared(p);
}

__device__ __forceinline__ void ldsm4(unsigned* d, unsigned addr)
{
    asm volatile("ldmatrix.sync.aligned.m8n8.x4.shared.b16 {%0,%1,%2,%3}, [%4];"
                 : "=r"(d[0]), "=r"(d[1]), "=r"(d[2]), "=r"(d[3]) : "r"(addr));
}

__device__ __forceinline__ void mma16816(float* c, const unsigned* a, const unsigned* b)
{
    asm volatile("mma.sync.aligned.m16n8k16.row.col.f32.bf16.bf16.f32 "
                 "{%0,%1,%2,%3},{%4,%5,%6,%7},{%8,%9},{%0,%1,%2,%3};"
                 : "+f"(c[0]), "+f"(c[1]), "+f"(c[2]), "+f"(c[3])
                 : "r"(a[0]), "r"(a[1]), "r"(a[2]), "r"(a[3]), "r"(b[0]), "r"(b[1]));
}

// ---------------------------------------------------------------------------
// Tensor-core GEMM (mma.sync + ldmatrix), fp32 I/O, bf16x3 emulation.
//   C[m,n] = sum_k A[m,k]*B[k,n].
//   A: K contiguous, row stride as_m.      (optional: A := relu(A + a_bias[k]))
//   B: K contiguous (pre-transposed), "row" = n, row stride bs_n.
//   Batch z = (bo*inner + bi)*ksplit + ks. Split-K chunk ks shifts A/B/bias
//   by ks*K and C by ks*c_slab (partial slabs reduced by reduce_add).
//   All M,N,K exact multiples of tiles. BK=32. 8 warps (WM*WN==8).
//   Single-stage static smem; next gmem tile prefetched into registers
//   between the two syncs so loads overlap the mma phase.
// ---------------------------------------------------------------------------
template<int BM, int BN, int WM, int WN>
__global__ __launch_bounds__(256)
void mgemm(const float* __restrict__ A, const float* __restrict__ Bm,
           const float* __restrict__ a_bias, float* __restrict__ C,
           int K,
           long as_m, long a_bso, long a_bsi,
           long bs_n, long b_bso, long b_bsi,
           long cs_m, long c_bso, long c_bsi,
           int inner, int ksplit, long c_slab)
{
    const int BK  = 32;
    const int LD  = 40;                  // 80B rows: ldmatrix conflict-free
    const int NRA = BM/32;               // float4 per thread for A tile
    const int NRB = BN/32;
    const int WTM = BM/WM;
    const int WTN = BN/WN;
    const int FM  = WTM/16;
    const int FN  = WTN/8;

    // (BM+BN)*LD/4 float4 = 2*(BM+BN)*LD bf16 (Ah|Al|Bh|Bl); float4 => 16B aligned
    __shared__ float4 smbuf[(BM + BN)*LD/4];
    __nv_bfloat16* sAh = (__nv_bfloat16*)smbuf;
    __nv_bfloat16* sAl = sAh + BM*LD;
    __nv_bfloat16* sBh = sAl + BM*LD;
    __nv_bfloat16* sBl = sBh + BN*LD;

    const int t    = threadIdx.x;
    const int warp = t >> 5;
    const int lane = t & 31;
    const int wm   = warp / WN;
    const int wn   = warp % WN;

    const int  ks = blockIdx.z % ksplit;
    const long zz = blockIdx.z / ksplit;
    const long bo = zz / inner;
    const long bi = zz % inner;
    const long m0 = (long)blockIdx.y * BM;
    const long n0 = (long)blockIdx.x * BN;

    const float* Ab = A  + bo*a_bso + bi*a_bsi + m0*as_m + (long)ks*K;
    const float* Bb = Bm + bo*b_bso + bi*b_bsi + n0*bs_n + (long)ks*K;
    const float* bias = a_bias ? (a_bias + (long)ks*K) : a_bias;

    // lane-derived ldmatrix offsets (elements, relative to fragment origin)
    const int qq = lane >> 3, rr = lane & 7;
    const int a_off = ((qq & 1)*8 + rr)*LD + (qq >> 1)*8;   // A: m halves, k halves
    const int b_off = ((qq >> 1)*8 + rr)*LD + (qq & 1)*8;   // B: n halves, k halves

    float acc[FM][FN][4];
#pragma unroll
    for (int i = 0; i < FM; ++i)
#pragma unroll
        for (int j = 0; j < FN; ++j)
#pragma unroll
            for (int r = 0; r < 4; ++r) acc[i][j][r] = 0.f;

    float4 ra[NRA], rb[NRB];

    // ---- prologue: load tile 0 into registers ----
#pragma unroll
    for (int i = 0; i < NRA; ++i) {
        int f = t + i*256, row = f >> 3, c4 = (f & 7)*4;
        float4 v = *(const float4*)(Ab + (long)row*as_m + c4);
        if (bias) {
            float4 bb = *(const float4*)(bias + c4);
            v.x = fmaxf(v.x + bb.x, 0.f); v.y = fmaxf(v.y + bb.y, 0.f);
            v.z = fmaxf(v.z + bb.z, 0.f); v.w = fmaxf(v.w + bb.w, 0.f);
        }
        ra[i] = v;
    }
#pragma unroll
    for (int i = 0; i < NRB; ++i) {
        int f = t + i*256, row = f >> 3, c4 = (f & 7)*4;
        rb[i] = *(const float4*)(Bb + (long)row*bs_n + c4);
    }

    const int iters = K / BK;
#pragma unroll 1
    for (int it = 0; it < iters; ++it) {
        // ---- store register tile -> smem (split hi/lo) ----
#pragma unroll
        for (int i = 0; i < NRA; ++i) {
            int f = t + i*256, row = f >> 3, c4 = (f & 7)*4;
            __nv_bfloat16 h0,h1,h2,h3,l0,l1,l2,l3;
            split_bf16(ra[i].x, h0, l0); split_bf16(ra[i].y, h1, l1);
            split_bf16(ra[i].z, h2, l2); split_bf16(ra[i].w, h3, l3);
            __nv_bfloat162 hv0; hv0.x = h0; hv0.y = h1;
            __nv_bfloat162 hv1; hv1.x = h2; hv1.y = h3;
            __nv_bfloat162 lv0; lv0.x = l0; lv0.y = l1;
            __nv_bfloat162 lv1; lv1.x = l2; lv1.y = l3;
            *(__nv_bfloat162*)(sAh + row*LD + c4)     = hv0;
            *(__nv_bfloat162*)(sAh + row*LD + c4 + 2) = hv1;
            *(__nv_bfloat162*)(sAl + row*LD + c4)     = lv0;
            *(__nv_bfloat162*)(sAl + row*LD + c4 + 2) = lv1;
        }
#pragma unroll
        for (int i = 0; i < NRB; ++i) {
            int f = t + i*256, row = f >> 3, c4 = (f & 7)*4;
            __nv_bfloat16 h0,h1,h2,h3,l0,l1,l2,l3;
            split_bf16(rb[i].x, h0, l0); split_bf16(rb[i].y, h1, l1);
            split_bf16(rb[i].z, h2, l2); split_bf16(rb[i].w, h3, l3);
            __nv_bfloat162 hv0; hv0.x = h0; hv0.y = h1;
            __nv_bfloat162 hv1; hv1.x = h2; hv1.y = h3;
            __nv_bfloat162 lv0; lv0.x = l0; lv0.y = l1;
            __nv_bfloat162 lv1; lv1.x = l2; lv1.y = l3;
            *(__nv_bfloat162*)(sBh + row*LD + c4)     = hv0;
            *(__nv_bfloat162*)(sBh + row*LD + c4 + 2) = hv1;
            *(__nv_bfloat162*)(sBl + row*LD + c4)     = lv0;
            *(__nv_bfloat162*)(sBl + row*LD + c4 + 2) = lv1;
        }
        __syncthreads();

        // ---- prefetch next tile into registers (overlaps mma phase) ----
        if (it + 1 < iters) {
            int k0 = (it + 1) * BK;
#pragma unroll
            for (int i = 0; i < NRA; ++i) {
                int f = t + i*256, row = f >> 3, c4 = (f & 7)*4;
                float4 v = *(const float4*)(Ab + (long)row*as_m + k0 + c4);
                if (bias) {
                    float4 bb = *(const float4*)(bias + k0 + c4);
                    v.x = fmaxf(v.x + bb.x, 0.f); v.y = fmaxf(v.y + bb.y, 0.f);
                    v.z = fmaxf(v.z + bb.z, 0.f); v.w = fmaxf(v.w + bb.w, 0.f);
                }
                ra[i] = v;
            }
#pragma unroll
            for (int i = 0; i < NRB; ++i) {
                int f = t + i*256, row = f >> 3, c4 = (f & 7)*4;
                rb[i] = *(const float4*)(Bb + (long)row*bs_n + k0 + c4);
            }
        }

        // ---- compute: 2 k-slices of 16, three emulation terms ----
#pragma unroll
        for (int ks2 = 0; ks2 < 2; ++ks2) {
            const int kb = ks2*16;
            unsigned ah[FM][4], al[FM][4], bh[FN][2], bl[FN][2], tmp[4];
#pragma unroll
            for (int fm = 0; fm < FM; ++fm) {
                ldsm4(ah[fm], smem_addr_u32(sAh + (wm*WTM + fm*16)*LD + kb + a_off));
                ldsm4(al[fm], smem_addr_u32(sAl + (wm*WTM + fm*16)*LD + kb + a_off));
            }
#pragma unroll
            for (int fg = 0; fg < FN/2; ++fg) {
                ldsm4(tmp, smem_addr_u32(sBh + (wn*WTN + fg*16)*LD + kb + b_off));
                bh[2*fg  ][0] = tmp[0]; bh[2*fg  ][1] = tmp[1];
                bh[2*fg+1][0] = tmp[2]; bh[2*fg+1][1] = tmp[3];
                ldsm4(tmp, smem_addr_u32(sBl + (wn*WTN + fg*16)*LD + kb + b_off));
                bl[2*fg  ][0] = tmp[0]; bl[2*fg  ][1] = tmp[1];
                bl[2*fg+1][0] = tmp[2]; bl[2*fg+1][1] = tmp[3];
            }
#pragma unroll
            for (int fm = 0; fm < FM; ++fm)
#pragma unroll
                for (int fn = 0; fn < FN; ++fn) {
                    mma16816(acc[fm][fn], ah[fm], bh[fn]);
                    mma16816(acc[fm][fn], ah[fm], bl[fn]);
                    mma16816(acc[fm][fn], al[fm], bh[fn]);
                }
        }
        __syncthreads();
    }

    // ---- epilogue ----
    const int g = lane >> 2, tig = lane & 3;
    float* Cb = C + bo*c_bso + bi*c_bsi + (long)ks*c_slab;
#pragma unroll
    for (int fm = 0; fm < FM; ++fm) {
#pragma unroll
        for (int fn = 0; fn < FN; ++fn) {
            float* p = Cb + (m0 + wm*WTM + fm*16 + g)*cs_m
                          + n0 + wn*WTN + fn*8 + 2*tig;
            float2 v0; v0.x = acc[fm][fn][0]; v0.y = acc[fm][fn][1];
            float2 v1; v1.x = acc[fm][fn][2]; v1.y = acc[fm][fn][3];
            *(float2*)p            = v0;
            *(float2*)(p + 8*cs_m) = v1;
        }
    }
}

// ---------------------------------------------------------------------------
// Edge-conditioned logits + softmax, fused. One CTA per (b, n). 256 threads
// (2 CTAs/SM; doubled load parallelism vs the 128-thread version).
//   logits[b,h,n,m] += sum_e qe[b,n,h,e] * edge[b,n,m,e]  ; softmax over m.
// ---------------------------------------------------------------------------
#define EDGE_SMEM_BYTES ((8192 + 256*17*4 + 128*4) * 4)   // 104448

__global__ __launch_bounds__(256)
void edge_softmax_kernel(const float* __restrict__ edge,
                         const float* __restrict__ qe,
                         float* __restrict__ logits)
{
    extern __shared__ float smem[];
    float*  s_logits = smem;                       // 8192 floats
    float4* s_edge4  = (float4*)(smem + 8192);     // 256*17 float4
    float4* s_qe4    = s_edge4 + 256*17;           // 128 float4

    const int t  = threadIdx.x;
    const int bn = blockIdx.x;
    const int b  = bn >> 10;
    const int n  = bn & 1023;

    if (t < 128) s_qe4[t] = ((const float4*)(qe + (long)bn*512))[t];

    // init s_logits with QK logits (256 float4 per head, 1 per thread)
    const float* lg = logits + ((long)(b*H_)*N_ + n) * N_;
#pragma unroll
    for (int h = 0; h < H_; ++h) {
        const float4* src = (const float4*)(lg + (long)h*N_*N_);
        ((float4*)(s_logits + h*N_))[t] = src[t];
    }
    __syncthreads();

    const float4* eg = (const float4*)(edge + ((long)bn << 16));
    const int tx = t & 63;            // m lane
    const int hg = t >> 6;            // head group 0..3 -> heads {2hg, 2hg+1}

    for (int mt = 0; mt < 4; ++mt) {
        // load edge tile rows [mt*256, mt*256+256): 4096 float4, 16 per thread
#pragma unroll 16
        for (int i = 0; i < 16; ++i) {
            int f   = t + i*256;
            int row = f >> 4, c = f & 15;
            s_edge4[row*17 + c] = eg[(mt*256 + row)*16 + c];
        }
        __syncthreads();

        float acc[4][2];
#pragma unroll
        for (int i = 0; i < 4; ++i) {
            acc[i][0] = 0.f; acc[i][1] = 0.f;
        }

#pragma unroll
        for (int e4 = 0; e4 < 16; ++e4) {
            float4 ev[4], qv[2];
#pragma unroll
            for (int i = 0; i < 4; ++i) ev[i] = s_edge4[(tx + i*64)*17 + e4];
            qv[0] = s_qe4[(hg*2 + 0)*16 + e4];
            qv[1] = s_qe4[(hg*2 + 1)*16 + e4];
#pragma unroll
            for (int i = 0; i < 4; ++i) {
                acc[i][0] += ev[i].x*qv[0].x + ev[i].y*qv[0].y
                           + ev[i].z*qv[0].z + ev[i].w*qv[0].w;
                acc[i][1] += ev[i].x*qv[1].x + ev[i].y*qv[1].y
                           + ev[i].z*qv[1].z + ev[i].w*qv[1].w;
            }
        }
#pragma unroll
        for (int j = 0; j < 2; ++j)
#pragma unroll
            for (int i = 0; i < 4; ++i)
                s_logits[(hg*2 + j)*N_ + mt*256 + i*64 + tx] += acc[i][j];
        __syncthreads();
    }

    // softmax: one warp per head (8 warps, 8 heads)
    const int warp = t >> 5, lane = t & 31;
    for (int h = warp; h < H_; h += 8) {
        const float* row = s_logits + h*N_;
        float mx = -1e30f;
#pragma unroll
        for (int i = 0; i < 32; ++i) mx = fmaxf(mx, row[lane + i*32]);
#pragma unroll
        for (int o = 16; o; o >>= 1) mx = fmaxf(mx, __shfl_xor_sync(~0u, mx, o));
        float vals[32];
        float sum = 0.f;
#pragma unroll
        for (int i = 0; i < 32; ++i) {
            vals[i] = __expf(row[lane + i*32] - mx);
            sum += vals[i];
        }
#pragma unroll
        for (int o = 16; o; o >>= 1) sum += __shfl_xor_sync(~0u, sum, o);
        const float inv = 1.f / sum;
        float* out = logits + ((long)(b*H_ + h)*N_ + n) * N_;
#pragma unroll
        for (int i = 0; i < 32; ++i) out[lane + i*32] = vals[i] * inv;
    }
}

// ---------------------------------------------------------------------------
// LayerNorm over last dim (256), fused residual + residual-bias.
// ---------------------------------------------------------------------------
__global__ __launch_bounds__(256)
void ln_kernel(const float* __restrict__ a, const float* __restrict__ r,
               const float* __restrict__ rb,
               const float* __restrict__ gam, const float* __restrict__ bet,
               float* __restrict__ out)
{
    const int warp = threadIdx.x >> 5, lane = threadIdx.x & 31;
    const long row = (long)blockIdx.x * 8 + warp;
    const float4* pa = (const float4*)(a + row*D_);
    const float4* pr = (const float4*)(r + row*D_);
    const float4 rb0 = ((const float4*)rb)[lane], rb1 = ((const float4*)rb)[lane + 32];
    float4 v0 = pa[lane], v1 = pa[lane + 32];
    const float4 q0 = pr[lane], q1 = pr[lane + 32];
    v0.x += q0.x + rb0.x; v0.y += q0.y + rb0.y; v0.z += q0.z + rb0.z; v0.w += q0.w + rb0.w;
    v1.x += q1.x + rb1.x; v1.y += q1.y + rb1.y; v1.z += q1.z + rb1.z; v1.w += q1.w + rb1.w;

    float s = v0.x + v0.y + v0.z + v0.w + v1.x + v1.y + v1.z + v1.w;
#pragma unroll
    for (int o = 16; o; o >>= 1) s += __shfl_xor_sync(~0u, s, o);
    const float mu = s * (1.f / 256.f);

    float4 d0, d1;
    d0.x = v0.x - mu; d0.y = v0.y - mu; d0.z = v0.z - mu; d0.w = v0.w - mu;
    d1.x = v1.x - mu; d1.y = v1.y - mu; d1.z = v1.z - mu; d1.w = v1.w - mu;
    float var = d0.x*d0.x + d0.y*d0.y + d0.z*d0.z + d0.w*d0.w
              + d1.x*d1.x + d1.y*d1.y + d1.z*d1.z + d1.w*d1.w;
#pragma unroll
    for (int o = 16; o; o >>= 1) var += __shfl_xor_sync(~0u, var, o);
    const float rs = rsqrtf(var * (1.f / 256.f) + 1e-6f);

    const float4 g0 = ((const float4*)gam)[lane], g1 = ((const float4*)gam)[lane + 32];
    const float4 bb0 = ((const float4*)bet)[lane], bb1 = ((const float4*)bet)[lane + 32];
    float4 o0, o1;
    o0.x = d0.x*rs*g0.x + bb0.x; o0.y = d0.y*rs*g0.y + bb0.y;
    o0.z = d0.z*rs*g0.z + bb0.z; o0.w = d0.w*rs*g0.w + bb0.w;
    o1.x = d1.x*rs*g1.x + bb1.x; o1.y = d1.y*rs*g1.y + bb1.y;
    o1.z = d1.z*rs*g1.z + bb1.z; o1.w = d1.w*rs*g1.w + bb1.w;
    ((float4*)(out + row*D_))[lane]      = o0;
    ((float4*)(out + row*D_))[lane + 32] = o1;
}

// ---------------------------------------------------------------------------
// Host launch (graph-capturable)
// ---------------------------------------------------------------------------
extern "C" void kernel_launch(void* const* d_in, const int* in_sizes, int n_in,
                              void* d_out, int out_size)
{
    const float* node = (const float*)d_in[0];
    const float* edge = (const float*)d_in[1];
    const float* Wq   = (const float*)d_in[2];
    const float* Wk   = (const float*)d_in[3];
    const float* Wv   = (const float*)d_in[4];
    const float* Wp   = (const float*)d_in[5];
    const float* bp   = (const float*)d_in[6];
    const float* ln1g = (const float*)d_in[7];
    const float* ln1b = (const float*)d_in[8];
    const float* W1   = (const float*)d_in[9];
    const float* b1   = (const float*)d_in[10];
    const float* W2   = (const float*)d_in[11];
    const float* b2   = (const float*)d_in[12];
    const float* ln2g = (const float*)d_in[13];
    const float* ln2b = (const float*)d_in[14];

    float *qkv, *qe, *logits, *mo, *mha, *x, *ffh, *ff;
    float *wqkvT, *WpT, *W1T, *W2T, *vT, *part;
    cudaGetSymbolAddress((void**)&qkv,    g_qkv);
    cudaGetSymbolAddress((void**)&qe,     g_qe);
    cudaGetSymbolAddress((void**)&logits, g_logits);
    cudaGetSymbolAddress((void**)&mo,     g_mo);
    cudaGetSymbolAddress((void**)&mha,    g_mha);
    cudaGetSymbolAddress((void**)&x,      g_x);
    cudaGetSymbolAddress((void**)&ffh,    g_ffh);
    cudaGetSymbolAddress((void**)&ff,     g_ff);
    cudaGetSymbolAddress((void**)&wqkvT,  g_wqkvT);
    cudaGetSymbolAddress((void**)&WpT,    g_WpT);
    cudaGetSymbolAddress((void**)&W1T,    g_W1T);
    cudaGetSymbolAddress((void**)&W2T,    g_W2T);
    cudaGetSymbolAddress((void**)&vT,     g_vT);
    cudaGetSymbolAddress((void**)&part,   g_part);

    cudaFuncSetAttribute(edge_softmax_kernel,
                         cudaFuncAttributeMaxDynamicSharedMemorySize, EDGE_SMEM_BYTES);

    // 0) weight repacks (transposed layouts; all B operands become k-contiguous)
    repack_wqkvT<<<(D_*QKV_ + 255)/256, 256>>>(Wq, Wk, Wv, wqkvT);
    transpose_k<<<dim3(D_/32, 512/32),  dim3(32,8)>>>(Wp, WpT, 512, D_);
    transpose_k<<<dim3(FF_/32, D_/32),  dim3(32,8)>>>(W1, W1T, D_, FF_);
    transpose_k<<<dim3(D_/32, FF_/32),  dim3(32,8)>>>(W2, W2T, FF_, D_);

    // 1) fused QKV projection split-K2: qkv = node @ wqkvT^T  (768 CTAs)
    mgemm<128,64,4,2><<<dim3(QKV_/64, R_/128, 2), 256>>>(
        node, wqkvT, (const float*)0, part, D_/2,
        D_, 0, 0,
        D_, 0, 0,
        QKV_, 0, 0, 1, 2, (long)R_*QKV_);
    reduce_add<<<(R_*QKV_/4 + 255)/256, 256>>>(part, qkv, R_*QKV_/4, 2, (long)R_*QKV_/4);

    // 1b) v transpose for AV's B operand
    vt_kernel<<<dim3(512/32, N_/32, B_), dim3(32,8)>>>(qkv, vT);

    // 2) qe[r][h*64+e] = q_h[r,:] @ WkE_h^T   (z = h; 256 CTAs)
    mgemm<64,64,2,4><<<dim3(1, R_/64, H_), 256>>>(
        qkv, Wk + (long)D_*HS_, (const float*)0, qe, HS_,
        QKV_, 64, 0,
        HS_, (long)(D_+E_)*HS_, 0,
        (long)H_*E_, 64, 0, 1, 1, 0);

    // 3) QK^T logits (z = b*8+h; 2048 CTAs)
    mgemm<128,64,4,2><<<dim3(N_/64, N_/128, B_*H_), 256>>>(
        qkv, qkv + 512, (const float*)0, logits, HS_,
        QKV_, (long)N_*QKV_, 64,
        QKV_, (long)N_*QKV_, 64,
        N_, (long)H_*N_*N_, (long)N_*N_, H_, 1, 0);

    // 4) edge logits + softmax (streams 536 MB; in-place probs)
    edge_softmax_kernel<<<R_, 256, EDGE_SMEM_BYTES>>>(edge, qe, logits);

    // 5) AV split-K4: part[ks] = attn[.., chunk] @ vT[chunk]  (1024 CTAs)
    mgemm<64,64,2,4><<<dim3(1, N_/64, B_*H_*4), 256>>>(
        logits, vT, (const float*)0, part, N_/4,
        N_, (long)H_*N_*N_, (long)N_*N_,
        N_, (long)512*N_, (long)64*N_,
        (long)H_*HS_, (long)N_*H_*HS_, 64, H_, 4, (long)R_*512);
    reduce_add<<<(R_*512/4 + 255)/256, 256>>>(part, mo, R_*512/4, 4, (long)R_*512/4);

    // 6) output projection split-K2: part[ks] = mo[..,ks] @ WpT[ks]  (256 CTAs)
    mgemm<64,64,2,4><<<dim3(D_/64, R_/64, 2), 256>>>(
        mo, WpT, (const float*)0, part, (H_*HS_)/2,
        (long)H_*HS_, 0, 0,
        (long)H_*HS_, 0, 0,
        D_, 0, 0, 1, 2, (long)R_*D_);
    reduce_add<<<(R_*D_/4 + 255)/256, 256>>>(part, mha, R_*D_/4, 2, (long)R_*D_/4);

    // 7) x = LN1(node + mha + bp)
    ln_kernel<<<R_/8, 256>>>(node, mha, bp, ln1g, ln1b, x);

    // 8) FFN hidden split-K2: ffh = x @ W1  (512 CTAs; b1+relu fused into step 9)
    mgemm<128,64,4,2><<<dim3(FF_/64, R_/128, 2), 256>>>(
        x, W1T, (const float*)0, part, D_/2,
        D_, 0, 0,
        D_, 0, 0,
        FF_, 0, 0, 1, 2, (long)R_*FF_);
    reduce_add<<<(R_*FF_/4 + 255)/256, 256>>>(part, ffh, R_*FF_/4, 2, (long)R_*FF_/4);

    // 9) FFN out split-K4: part[ks] = relu(ffh+b1)[ks] @ W2T[ks]  (512 CTAs)
    mgemm<64,64,2,4><<<dim3(D_/64, R_/64, 4), 256>>>(
        ffh, W2T, b1, part, FF_/4,
        FF_, 0, 0,
        FF_, 0, 0,
        D_, 0, 0, 1, 4, (long)R_*D_);
    reduce_add<<<(R_*D_/4 + 255)/256, 256>>>(part, ff, R_*D_/4, 4, (long)R_*D_/4);

    // 10) out = LN2(x + ff + b2)
    ln_kernel<<<R_/8, 256>>>(x, ff, b2, ln2g, ln2b, (float*)d_out);
}

// round 12
// speedup vs baseline: 1.0055x; 1.0055x over previous
#include <cuda_runtime.h>
#include <cuda_bf16.h>

// Shapes (compile-time; problem is fixed-shape)
#define B_   2
#define N_   1024
#define D_   256
#define E_   64
#define H_   8
#define HS_  64
#define FF_  1024
#define R_   (B_*N_)        // 2048 token rows
#define QKV_ (3*H_*HS_)     // 1536

// ---------------------------------------------------------------------------
// Scratch (device globals; no runtime allocation allowed)
// ---------------------------------------------------------------------------
__device__ float g_qkv[R_*QKV_];                    // q | kn | v   (12 MB)
__device__ float g_qe[R_*H_*E_];                    // 4 MB
__device__ float g_logits[(long)B_*H_*N_*N_];       // 64 MB (reused as attn probs)
__device__ float g_mo[R_*H_*HS_];                   // 4 MB
__device__ float g_mha[R_*D_];                      // 2 MB
__device__ float g_x[R_*D_];                        // 2 MB
__device__ float g_ffh[R_*FF_];                     // 8 MB
__device__ float g_ff[R_*D_];                       // 2 MB
__device__ float g_wqkvT[QKV_*D_];                  // [1536][256]
__device__ float g_WpT[D_*H_*HS_];                  // [256][512]
__device__ float g_W1T[FF_*D_];                     // [1024][256]
__device__ float g_W2T[D_*FF_];                     // [256][1024]
__device__ float g_vT[(long)B_*H_*HS_*N_];          // [b][h*64+o][m]  4 MB
__device__ float g_part[2*R_*QKV_];                 // 25 MB split-K partials

// ---------------------------------------------------------------------------
// Repack Wq (scaled by 1/sqrt(HS)), Wk[:, :D], Wv into TRANSPOSED [1536][256]
// ---------------------------------------------------------------------------
__global__ void repack_wqkvT(const float* __restrict__ Wq,
                             const float* __restrict__ Wk,
                             const float* __restrict__ Wv,
                             float* __restrict__ out)
{
    int idx = blockIdx.x * blockDim.x + threadIdx.x;   // idx = j*256 + i
    if (idx >= D_ * QKV_) return;
    int j = idx / D_;        // output column of fused proj (0..1535)
    int i = idx % D_;        // input feature (0..255)
    float v;
    if (j < 512) {
        int h = j >> 6, o = j & 63;
        v = Wq[(h*D_ + i)*HS_ + o] * 0.125f;               // 1/sqrt(64)
    } else if (j < 1024) {
        int jj = j - 512; int h = jj >> 6, o = jj & 63;
        v = Wk[(h*(D_+E_) + i)*HS_ + o];
    } else {
        int jj = j - 1024; int h = jj >> 6, o = jj & 63;
        v = Wv[(h*D_ + i)*HS_ + o];
    }
    out[idx] = v;
}

// ---------------------------------------------------------------------------
// Generic tiled transpose: in[Rr][Cc] -> out[Cc][Rr]. Rr, Cc multiples of 32.
// ---------------------------------------------------------------------------
__global__ void transpose_k(const float* __restrict__ in, float* __restrict__ out,
                            int Rr, int Cc)
{
    __shared__ float tile[32][33];
    int x = blockIdx.x*32 + threadIdx.x;
    int y0 = blockIdx.y*32;
#pragma unroll
    for (int j = 0; j < 32; j += 8)
        tile[threadIdx.y + j][threadIdx.x] = in[(long)(y0 + threadIdx.y + j)*Cc + x];
    __syncthreads();
    int ox = y0 + threadIdx.x;
    int oy0 = blockIdx.x*32;
#pragma unroll
    for (int j = 0; j < 32; j += 8)
        out[(long)(oy0 + threadIdx.y + j)*Rr + ox] = tile[threadIdx.x][threadIdx.y + j];
}

// ---------------------------------------------------------------------------
// vT[b][c][m] = qkv[b*1024 + m][1024 + c]   (c = h*64+o, m = token)
// ---------------------------------------------------------------------------
__global__ void vt_kernel(const float* __restrict__ qkv, float* __restrict__ vT)
{
    __shared__ float tile[32][33];
    int b  = blockIdx.z;
    int c0 = blockIdx.x*32;
    int m0 = blockIdx.y*32;
#pragma unroll
    for (int j = 0; j < 32; j += 8)
        tile[threadIdx.y + j][threadIdx.x] =
            qkv[(long)(b*N_ + m0 + threadIdx.y + j)*QKV_ + 1024 + c0 + threadIdx.x];
    __syncthreads();
#pragma unroll
    for (int j = 0; j < 32; j += 8)
        vT[(long)(b*512 + c0 + threadIdx.y + j)*N_ + m0 + threadIdx.x] =
            tile[threadIdx.x][threadIdx.y + j];
}

// ---------------------------------------------------------------------------
// Deterministic slab reduction: out[i] = sum_j part[i + j*slab4] (float4 units)
// ---------------------------------------------------------------------------
__global__ void reduce_add(const float* __restrict__ part, float* __restrict__ out,
                           int n4, int nslab, long slab4)
{
    int i = blockIdx.x * blockDim.x + threadIdx.x;
    if (i >= n4) return;
    const float4* pp = (const float4*)part;
    float4 s = pp[i];
    for (int j = 1; j < nslab; ++j) {
        float4 v = pp[i + (long)j*slab4];
        s.x += v.x; s.y += v.y; s.z += v.z; s.w += v.w;
    }
    ((float4*)out)[i] = s;
}

// ---------------------------------------------------------------------------
// bf16 helpers / PTX wrappers
// ---------------------------------------------------------------------------
__device__ __forceinline__ void split_bf16(float v, __nv_bfloat16& h, __nv_bfloat16& l)
{
    h = __float2bfloat16(v);
    l = __float2bfloat16(v - __bfloat162float(h));
}

__device__ __forceinline__ unsigned smem_addr_u32(const void* p)
{
    return (unsigned)__cvta_generic_to_shared(p);
}

__device__ __forceinline__ void ldsm4(unsigned* d, unsigned addr)
{
    asm volatile("ldmatrix.sync.aligned.m8n8.x4.shared.b16 {%0,%1,%2,%3}, [%4];"
                 : "=r"(d[0]), "=r"(d[1]), "=r"(d[2]), "=r"(d[3]) : "r"(addr));
}

__device__ __forceinline__ void mma16816(float* c, const unsigned* a, const unsigned* b)
{
    asm volatile("mma.sync.aligned.m16n8k16.row.col.f32.bf16.bf16.f32 "
                 "{%0,%1,%2,%3},{%4,%5,%6,%7},{%8,%9},{%0,%1,%2,%3};"
                 : "+f"(c[0]), "+f"(c[1]), "+f"(c[2]), "+f"(c[3])
                 : "r"(a[0]), "r"(a[1]), "r"(a[2]), "r"(a[3]), "r"(b[0]), "r"(b[1]));
}

// ---------------------------------------------------------------------------
// Tensor-core GEMM (mma.sync + ldmatrix), fp32 I/O, bf16x3 emulation.
//   C[m,n] = sum_k A[m,k]*B[k,n].
//   A: K contiguous, row stride as_m.      (optional: A := relu(A + a_bias[k]))
//   B: K contiguous (pre-transposed), "row" = n, row stride bs_n.
//   Batch z = (bo*inner + bi)*ksplit + ks. Split-K chunk ks shifts A/B/bias
//   by ks*K and C by ks*c_slab (partial slabs reduced by reduce_add).
//   All M,N,K exact multiples of tiles. BK=32. 8 warps (WM*WN==8).
//   Single-stage static smem; next gmem tile prefetched into registers
//   between the two syncs so loads overlap the mma phase.
// ---------------------------------------------------------------------------
template<int BM, int BN, int WM, int WN>
__global__ __launch_bounds__(256)
void mgemm(const float* __restrict__ A, const float* __restrict__ Bm,
           const float* __restrict__ a_bias, float* __restrict__ C,
           int K,
           long as_m, long a_bso, long a_bsi,
           long bs_n, long b_bso, long b_bsi,
           long cs_m, long c_bso, long c_bsi,
           int inner, int ksplit, long c_slab)
{
    const int BK  = 32;
    const int LD  = 40;                  // 80B rows: ldmatrix conflict-free
    const int NRA = BM/32;               // float4 per thread for A tile
    const int NRB = BN/32;
    const int WTM = BM/WM;
    const int WTN = BN/WN;
    const int FM  = WTM/16;
    const int FN  = WTN/8;

    // (BM+BN)*LD/4 float4 = 2*(BM+BN)*LD bf16 (Ah|Al|Bh|Bl); float4 => 16B aligned
    __shared__ float4 smbuf[(BM + BN)*LD/4];
    __nv_bfloat16* sAh = (__nv_bfloat16*)smbuf;
    __nv_bfloat16* sAl = sAh + BM*LD;
    __nv_bfloat16* sBh = sAl + BM*LD;
    __nv_bfloat16* sBl = sBh + BN*LD;

    const int t    = threadIdx.x;
    const int warp = t >> 5;
    const int lane = t & 31;
    const int wm   = warp / WN;
    const int wn   = warp % WN;

    const int  ks = blockIdx.z % ksplit;
    const long zz = blockIdx.z / ksplit;
    const long bo = zz / inner;
    const long bi = zz % inner;
    const long m0 = (long)blockIdx.y * BM;
    const long n0 = (long)blockIdx.x * BN;

    const float* Ab = A  + bo*a_bso + bi*a_bsi + m0*as_m + (long)ks*K;
    const float* Bb = Bm + bo*b_bso + bi*b_bsi + n0*bs_n + (long)ks*K;
    const float* bias = a_bias ? (a_bias + (long)ks*K) : a_bias;

    // lane-derived ldmatrix offsets (elements, relative to fragment origin)
    const int qq = lane >> 3, rr = lane & 7;
    const int a_off = ((qq & 1)*8 + rr)*LD + (qq >> 1)*8;   // A: m halves, k halves
    const int b_off = ((qq >> 1)*8 + rr)*LD + (qq & 1)*8;   // B: n halves, k halves

    float acc[FM][FN][4];
#pragma unroll
    for (int i = 0; i < FM; ++i)
#pragma unroll
        for (int j = 0; j < FN; ++j)
#pragma unroll
            for (int r = 0; r < 4; ++r) acc[i][j][r] = 0.f;

    float4 ra[NRA], rb[NRB];

    // ---- prologue: load tile 0 into registers ----
#pragma unroll
    for (int i = 0; i < NRA; ++i) {
        int f = t + i*256, row = f >> 3, c4 = (f & 7)*4;
        float4 v = *(const float4*)(Ab + (long)row*as_m + c4);
        if (bias) {
            float4 bb = *(const float4*)(bias + c4);
            v.x = fmaxf(v.x + bb.x, 0.f); v.y = fmaxf(v.y + bb.y, 0.f);
            v.z = fmaxf(v.z + bb.z, 0.f); v.w = fmaxf(v.w + bb.w, 0.f);
        }
        ra[i] = v;
    }
#pragma unroll
    for (int i = 0; i < NRB; ++i) {
        int f = t + i*256, row = f >> 3, c4 = (f & 7)*4;
        rb[i] = *(const float4*)(Bb + (long)row*bs_n + c4);
    }

    const int iters = K / BK;
#pragma unroll 1
    for (int it = 0; it < iters; ++it) {
        // ---- store register tile -> smem (split hi/lo) ----
#pragma unroll
        for (int i = 0; i < NRA; ++i) {
            int f = t + i*256, row = f >> 3, c4 = (f & 7)*4;
            __nv_bfloat16 h0,h1,h2,h3,l0,l1,l2,l3;
            split_bf16(ra[i].x, h0, l0); split_bf16(ra[i].y, h1, l1);
            split_bf16(ra[i].z, h2, l2); split_bf16(ra[i].w, h3, l3);
            __nv_bfloat162 hv0; hv0.x = h0; hv0.y = h1;
            __nv_bfloat162 hv1; hv1.x = h2; hv1.y = h3;
            __nv_bfloat162 lv0; lv0.x = l0; lv0.y = l1;
            __nv_bfloat162 lv1; lv1.x = l2; lv1.y = l3;
            *(__nv_bfloat162*)(sAh + row*LD + c4)     = hv0;
            *(__nv_bfloat162*)(sAh + row*LD + c4 + 2) = hv1;
            *(__nv_bfloat162*)(sAl + row*LD + c4)     = lv0;
            *(__nv_bfloat162*)(sAl + row*LD + c4 + 2) = lv1;
        }
#pragma unroll
        for (int i = 0; i < NRB; ++i) {
            int f = t + i*256, row = f >> 3, c4 = (f & 7)*4;
            __nv_bfloat16 h0,h1,h2,h3,l0,l1,l2,l3;
            split_bf16(rb[i].x, h0, l0); split_bf16(rb[i].y, h1, l1);
            split_bf16(rb[i].z, h2, l2); split_bf16(rb[i].w, h3, l3);
            __nv_bfloat162 hv0; hv0.x = h0; hv0.y = h1;
            __nv_bfloat162 hv1; hv1.x = h2; hv1.y = h3;
            __nv_bfloat162 lv0; lv0.x = l0; lv0.y = l1;
            __nv_bfloat162 lv1; lv1.x = l2; lv1.y = l3;
            *(__nv_bfloat162*)(sBh + row*LD + c4)     = hv0;
            *(__nv_bfloat162*)(sBh + row*LD + c4 + 2) = hv1;
            *(__nv_bfloat162*)(sBl + row*LD + c4)     = lv0;
            *(__nv_bfloat162*)(sBl + row*LD + c4 + 2) = lv1;
        }
        __syncthreads();

        // ---- prefetch next tile into registers (overlaps mma phase) ----
        if (it + 1 < iters) {
            int k0 = (it + 1) * BK;
#pragma unroll
            for (int i = 0; i < NRA; ++i) {
                int f = t + i*256, row = f >> 3, c4 = (f & 7)*4;
                float4 v = *(const float4*)(Ab + (long)row*as_m + k0 + c4);
                if (bias) {
                    float4 bb = *(const float4*)(bias + k0 + c4);
                    v.x = fmaxf(v.x + bb.x, 0.f); v.y = fmaxf(v.y + bb.y, 0.f);
                    v.z = fmaxf(v.z + bb.z, 0.f); v.w = fmaxf(v.w + bb.w, 0.f);
                }
                ra[i] = v;
            }
#pragma unroll
            for (int i = 0; i < NRB; ++i) {
                int f = t + i*256, row = f >> 3, c4 = (f & 7)*4;
                rb[i] = *(const float4*)(Bb + (long)row*bs_n + k0 + c4);
            }
        }

        // ---- compute: 2 k-slices of 16, three emulation terms ----
#pragma unroll
        for (int ks2 = 0; ks2 < 2; ++ks2) {
            const int kb = ks2*16;
            unsigned ah[FM][4], al[FM][4], bh[FN][2], bl[FN][2], tmp[4];
#pragma unroll
            for (int fm = 0; fm < FM; ++fm) {
                ldsm4(ah[fm], smem_addr_u32(sAh + (wm*WTM + fm*16)*LD + kb + a_off));
                ldsm4(al[fm], smem_addr_u32(sAl + (wm*WTM + fm*16)*LD + kb + a_off));
            }
#pragma unroll
            for (int fg = 0; fg < FN/2; ++fg) {
                ldsm4(tmp, smem_addr_u32(sBh + (wn*WTN + fg*16)*LD + kb + b_off));
                bh[2*fg  ][0] = tmp[0]; bh[2*fg  ][1] = tmp[1];
                bh[2*fg+1][0] = tmp[2]; bh[2*fg+1][1] = tmp[3];
                ldsm4(tmp, smem_addr_u32(sBl + (wn*WTN + fg*16)*LD + kb + b_off));
                bl[2*fg  ][0] = tmp[0]; bl[2*fg  ][1] = tmp[1];
                bl[2*fg+1][0] = tmp[2]; bl[2*fg+1][1] = tmp[3];
            }
#pragma unroll
            for (int fm = 0; fm < FM; ++fm)
#pragma unroll
                for (int fn = 0; fn < FN; ++fn) {
                    mma16816(acc[fm][fn], ah[fm], bh[fn]);
                    mma16816(acc[fm][fn], ah[fm], bl[fn]);
                    mma16816(acc[fm][fn], al[fm], bh[fn]);
                }
        }
        __syncthreads();
    }

    // ---- epilogue ----
    const int g = lane >> 2, tig = lane & 3;
    float* Cb = C + bo*c_bso + bi*c_bsi + (long)ks*c_slab;
#pragma unroll
    for (int fm = 0; fm < FM; ++fm) {
#pragma unroll
        for (int fn = 0; fn < FN; ++fn) {
            float* p = Cb + (m0 + wm*WTM + fm*16 + g)*cs_m
                          + n0 + wn*WTN + fn*8 + 2*tig;
            float2 v0; v0.x = acc[fm][fn][0]; v0.y = acc[fm][fn][1];
            float2 v1; v1.x = acc[fm][fn][2]; v1.y = acc[fm][fn][3];
            *(float2*)p            = v0;
            *(float2*)(p + 8*cs_m) = v1;
        }
    }
}

// ---------------------------------------------------------------------------
// Edge-conditioned logits + softmax, fused. One CTA per (b, n). 256 threads
// (2 CTAs/SM; doubled load parallelism vs the 128-thread version).
//   logits[b,h,n,m] += sum_e qe[b,n,h,e] * edge[b,n,m,e]  ; softmax over m.
// ---------------------------------------------------------------------------
#define EDGE_SMEM_BYTES ((8192 + 256*17*4 + 128*4) * 4)   // 104448

__global__ __launch_bounds__(256)
void edge_softmax_kernel(const float* __restrict__ edge,
                         const float* __restrict__ qe,
                         float* __restrict__ logits)
{
    extern __shared__ float smem[];
    float*  s_logits = smem;                       // 8192 floats
    float4* s_edge4  = (float4*)(smem + 8192);     // 256*17 float4
    float4* s_qe4    = s_edge4 + 256*17;           // 128 float4

    const int t  = threadIdx.x;
    const int bn = blockIdx.x;
    const int b  = bn >> 10;
    const int n  = bn & 1023;

    if (t < 128) s_qe4[t] = ((const float4*)(qe + (long)bn*512))[t];

    // init s_logits with QK logits (256 float4 per head, 1 per thread)
    const float* lg = logits + ((long)(b*H_)*N_ + n) * N_;
#pragma unroll
    for (int h = 0; h < H_; ++h) {
        const float4* src = (const float4*)(lg + (long)h*N_*N_);
        ((float4*)(s_logits + h*N_))[t] = src[t];
    }
    __syncthreads();

    const float4* eg = (const float4*)(edge + ((long)bn << 16));
    const int tx = t & 63;            // m lane
    const int hg = t >> 6;            // head group 0..3 -> heads {2hg, 2hg+1}

    for (int mt = 0; mt < 4; ++mt) {
        // load edge tile rows [mt*256, mt*256+256): 4096 float4, 16 per thread
#pragma unroll 16
        for (int i = 0; i < 16; ++i) {
            int f   = t + i*256;
            int row = f >> 4, c = f & 15;
            s_edge4[row*17 + c] = eg[(mt*256 + row)*16 + c];
        }
        __syncthreads();

        float acc[4][2];
#pragma unroll
        for (int i = 0; i < 4; ++i) {
            acc[i][0] = 0.f; acc[i][1] = 0.f;
        }

#pragma unroll
        for (int e4 = 0; e4 < 16; ++e4) {
            float4 ev[4], qv[2];
#pragma unroll
            for (int i = 0; i < 4; ++i) ev[i] = s_edge4[(tx + i*64)*17 + e4];
            qv[0] = s_qe4[(hg*2 + 0)*16 + e4];
            qv[1] = s_qe4[(hg*2 + 1)*16 + e4];
#pragma unroll
            for (int i = 0; i < 4; ++i) {
                acc[i][0] += ev[i].x*qv[0].x + ev[i].y*qv[0].y
                           + ev[i].z*qv[0].z + ev[i].w*qv[0].w;
                acc[i][1] += ev[i].x*qv[1].x + ev[i].y*qv[1].y
                           + ev[i].z*qv[1].z + ev[i].w*qv[1].w;
            }
        }
#pragma unroll
        for (int j = 0; j < 2; ++j)
#pragma unroll
            for (int i = 0; i < 4; ++i)
                s_logits[(hg*2 + j)*N_ + mt*256 + i*64 + tx] += acc[i][j];
        __syncthreads();
    }

    // softmax: one warp per head (8 warps, 8 heads)
    const int warp = t >> 5, lane = t & 31;
    for (int h = warp; h < H_; h += 8) {
        const float* row = s_logits + h*N_;
        float mx = -1e30f;
#pragma unroll
        for (int i = 0; i < 32; ++i) mx = fmaxf(mx, row[lane + i*32]);
#pragma unroll
        for (int o = 16; o; o >>= 1) mx = fmaxf(mx, __shfl_xor_sync(~0u, mx, o));
        float vals[32];
        float sum = 0.f;
#pragma unroll
        for (int i = 0; i < 32; ++i) {
            vals[i] = __expf(row[lane + i*32] - mx);
            sum += vals[i];
        }
#pragma unroll
        for (int o = 16; o; o >>= 1) sum += __shfl_xor_sync(~0u, sum, o);
        const float inv = 1.f / sum;
        float* out = logits + ((long)(b*H_ + h)*N_ + n) * N_;
#pragma unroll
        for (int i = 0; i < 32; ++i) out[lane + i*32] = vals[i] * inv;
    }
}

// ---------------------------------------------------------------------------
// LayerNorm over last dim (256), fused residual + residual-bias.
// ---------------------------------------------------------------------------
__global__ __launch_bounds__(256)
void ln_kernel(const float* __restrict__ a, const float* __restrict__ r,
               const float* __restrict__ rb,
               const float* __restrict__ gam, const float* __restrict__ bet,
               float* __restrict__ out)
{
    const int warp = threadIdx.x >> 5, lane = threadIdx.x & 31;
    const long row = (long)blockIdx.x * 8 + warp;
    const float4* pa = (const float4*)(a + row*D_);
    const float4* pr = (const float4*)(r + row*D_);
    const float4 rb0 = ((const float4*)rb)[lane], rb1 = ((const float4*)rb)[lane + 32];
    float4 v0 = pa[lane], v1 = pa[lane + 32];
    const float4 q0 = pr[lane], q1 = pr[lane + 32];
    v0.x += q0.x + rb0.x; v0.y += q0.y + rb0.y; v0.z += q0.z + rb0.z; v0.w += q0.w + rb0.w;
    v1.x += q1.x + rb1.x; v1.y += q1.y + rb1.y; v1.z += q1.z + rb1.z; v1.w += q1.w + rb1.w;

    float s = v0.x + v0.y + v0.z + v0.w + v1.x + v1.y + v1.z + v1.w;
#pragma unroll
    for (int o = 16; o; o >>= 1) s += __shfl_xor_sync(~0u, s, o);
    const float mu = s * (1.f / 256.f);

    float4 d0, d1;
    d0.x = v0.x - mu; d0.y = v0.y - mu; d0.z = v0.z - mu; d0.w = v0.w - mu;
    d1.x = v1.x - mu; d1.y = v1.y - mu; d1.z = v1.z - mu; d1.w = v1.w - mu;
    float var = d0.x*d0.x + d0.y*d0.y + d0.z*d0.z + d0.w*d0.w
              + d1.x*d1.x + d1.y*d1.y + d1.z*d1.z + d1.w*d1.w;
#pragma unroll
    for (int o = 16; o; o >>= 1) var += __shfl_xor_sync(~0u, var, o);
    const float rs = rsqrtf(var * (1.f / 256.f) + 1e-6f);

    const float4 g0 = ((const float4*)gam)[lane], g1 = ((const float4*)gam)[lane + 32];
    const float4 bb0 = ((const float4*)bet)[lane], bb1 = ((const float4*)bet)[lane + 32];
    float4 o0, o1;
    o0.x = d0.x*rs*g0.x + bb0.x; o0.y = d0.y*rs*g0.y + bb0.y;
    o0.z = d0.z*rs*g0.z + bb0.z; o0.w = d0.w*rs*g0.w + bb0.w;
    o1.x = d1.x*rs*g1.x + bb1.x; o1.y = d1.y*rs*g1.y + bb1.y;
    o1.z = d1.z*rs*g1.z + bb1.z; o1.w = d1.w*rs*g1.w + bb1.w;
    ((float4*)(out + row*D_))[lane]      = o0;
    ((float4*)(out + row*D_))[lane + 32] = o1;
}

// ---------------------------------------------------------------------------
// Host launch (graph-capturable)
// ---------------------------------------------------------------------------
extern "C" void kernel_launch(void* const* d_in, const int* in_sizes, int n_in,
                              void* d_out, int out_size)
{
    const float* node = (const float*)d_in[0];
    const float* edge = (const float*)d_in[1];
    const float* Wq   = (const float*)d_in[2];
    const float* Wk   = (const float*)d_in[3];
    const float* Wv   = (const float*)d_in[4];
    const float* Wp   = (const float*)d_in[5];
    const float* bp   = (const float*)d_in[6];
    const float* ln1g = (const float*)d_in[7];
    const float* ln1b = (const float*)d_in[8];
    const float* W1   = (const float*)d_in[9];
    const float* b1   = (const float*)d_in[10];
    const float* W2   = (const float*)d_in[11];
    const float* b2   = (const float*)d_in[12];
    const float* ln2g = (const float*)d_in[13];
    const float* ln2b = (const float*)d_in[14];

    float *qkv, *qe, *logits, *mo, *mha, *x, *ffh, *ff;
    float *wqkvT, *WpT, *W1T, *W2T, *vT, *part;
    cudaGetSymbolAddress((void**)&qkv,    g_qkv);
    cudaGetSymbolAddress((void**)&qe,     g_qe);
    cudaGetSymbolAddress((void**)&logits, g_logits);
    cudaGetSymbolAddress((void**)&mo,     g_mo);
    cudaGetSymbolAddress((void**)&mha,    g_mha);
    cudaGetSymbolAddress((void**)&x,      g_x);
    cudaGetSymbolAddress((void**)&ffh,    g_ffh);
    cudaGetSymbolAddress((void**)&ff,     g_ff);
    cudaGetSymbolAddress((void**)&wqkvT,  g_wqkvT);
    cudaGetSymbolAddress((void**)&WpT,    g_WpT);
    cudaGetSymbolAddress((void**)&W1T,    g_W1T);
    cudaGetSymbolAddress((void**)&W2T,    g_W2T);
    cudaGetSymbolAddress((void**)&vT,     g_vT);
    cudaGetSymbolAddress((void**)&part,   g_part);

    cudaFuncSetAttribute(edge_softmax_kernel,
                         cudaFuncAttributeMaxDynamicSharedMemorySize, EDGE_SMEM_BYTES);

    // 0) weight repacks (transposed layouts; all B operands become k-contiguous)
    repack_wqkvT<<<(D_*QKV_ + 255)/256, 256>>>(Wq, Wk, Wv, wqkvT);
    transpose_k<<<dim3(D_/32, 512/32),  dim3(32,8)>>>(Wp, WpT, 512, D_);
    transpose_k<<<dim3(FF_/32, D_/32),  dim3(32,8)>>>(W1, W1T, D_, FF_);
    transpose_k<<<dim3(D_/32, FF_/32),  dim3(32,8)>>>(W2, W2T, FF_, D_);

    // 1) fused QKV projection split-K2: qkv = node @ wqkvT^T  (768 CTAs)
    mgemm<128,64,4,2><<<dim3(QKV_/64, R_/128, 2), 256>>>(
        node, wqkvT, (const float*)0, part, D_/2,
        D_, 0, 0,
        D_, 0, 0,
        QKV_, 0, 0, 1, 2, (long)R_*QKV_);
    reduce_add<<<(R_*QKV_/4 + 255)/256, 256>>>(part, qkv, R_*QKV_/4, 2, (long)R_*QKV_/4);

    // 1b) v transpose for AV's B operand
    vt_kernel<<<dim3(512/32, N_/32, B_), dim3(32,8)>>>(qkv, vT);

    // 2) qe[r][h*64+e] = q_h[r,:] @ WkE_h^T   (z = h; 256 CTAs)
    mgemm<64,64,2,4><<<dim3(1, R_/64, H_), 256>>>(
        qkv, Wk + (long)D_*HS_, (const float*)0, qe, HS_,
        QKV_, 64, 0,
        HS_, (long)(D_+E_)*HS_, 0,
        (long)H_*E_, 64, 0, 1, 1, 0);

    // 3) QK^T logits (z = b*8+h; 2048 CTAs)
    mgemm<128,64,4,2><<<dim3(N_/64, N_/128, B_*H_), 256>>>(
        qkv, qkv + 512, (const float*)0, logits, HS_,
        QKV_, (long)N_*QKV_, 64,
        QKV_, (long)N_*QKV_, 64,
        N_, (long)H_*N_*N_, (long)N_*N_, H_, 1, 0);

    // 4) edge logits + softmax (streams 536 MB; in-place probs)
    edge_softmax_kernel<<<R_, 256, EDGE_SMEM_BYTES>>>(edge, qe, logits);

    // 5) AV split-K4: part[ks] = attn[.., chunk] @ vT[chunk]  (1024 CTAs)
    mgemm<64,64,2,4><<<dim3(1, N_/64, B_*H_*4), 256>>>(
        logits, vT, (const float*)0, part, N_/4,
        N_, (long)H_*N_*N_, (long)N_*N_,
        N_, (long)512*N_, (long)64*N_,
        (long)H_*HS_, (long)N_*H_*HS_, 64, H_, 4, (long)R_*512);
    reduce_add<<<(R_*512/4 + 255)/256, 256>>>(part, mo, R_*512/4, 4, (long)R_*512/4);

    // 6) output projection split-K2: part[ks] = mo[..,ks] @ WpT[ks]  (256 CTAs)
    mgemm<64,64,2,4><<<dim3(D_/64, R_/64, 2), 256>>>(
        mo, WpT, (const float*)0, part, (H_*HS_)/2,
        (long)H_*HS_, 0, 0,
        (long)H_*HS_, 0, 0,
        D_, 0, 0, 1, 2, (long)R_*D_);
    reduce_add<<<(R_*D_/4 + 255)/256, 256>>>(part, mha, R_*D_/4, 2, (long)R_*D_/4);

    // 7) x = LN1(node + mha + bp)
    ln_kernel<<<R_/8, 256>>>(node, mha, bp, ln1g, ln1b, x);

    // 8) FFN hidden split-K2: ffh = x @ W1  (512 CTAs; b1+relu fused into step 9)
    mgemm<128,64,4,2><<<dim3(FF_/64, R_/128, 2), 256>>>(
        x, W1T, (const float*)0, part, D_/2,
        D_, 0, 0,
        D_, 0, 0,
        FF_, 0, 0, 1, 2, (long)R_*FF_);
    reduce_add<<<(R_*FF_/4 + 255)/256, 256>>>(part, ffh, R_*FF_/4, 2, (long)R_*FF_/4);

    // 9) FFN out split-K4: part[ks] = relu(ffh+b1)[ks] @ W2T[ks]  (512 CTAs)
    mgemm<64,64,2,4><<<dim3(D_/64, R_/64, 4), 256>>>(
        ffh, W2T, b1, part, FF_/4,
        FF_, 0, 0,
        FF_, 0, 0,
        D_, 0, 0, 1, 4, (long)R_*D_);
    reduce_add<<<(R_*D_/4 + 255)/256, 256>>>(part, ff, R_*D_/4, 4, (long)R_*D_/4);

    // 10) out = LN2(x + ff + b2)
    ln_kernel<<<R_/8, 256>>>(x, ff, b2, ln2g, ln2b, (float*)d_out);
}

// round 13
// speedup vs baseline: 1.0313x; 1.0257x over previous
#include <cuda_runtime.h>
#include <cuda_bf16.h>

// Shapes (compile-time; problem is fixed-shape)
#define B_   2
#define N_   1024
#define D_   256
#define E_   64
#define H_   8
#define HS_  64
#define FF_  1024
#define R_   (B_*N_)        // 2048 token rows
#define QKV_ (3*H_*HS_)     // 1536

// ---------------------------------------------------------------------------
// Scratch (device globals; no runtime allocation allowed)
// ---------------------------------------------------------------------------
__device__ float g_qkv[R_*QKV_];                    // q | kn | v   (12 MB)
__device__ float g_qe[R_*H_*E_];                    // 4 MB
__device__ float g_logits[(long)B_*H_*N_*N_];       // 64 MB (reused as attn probs)
__device__ float g_mo[R_*H_*HS_];                   // 4 MB
__device__ float g_mha[R_*D_];                      // 2 MB
__device__ float g_x[R_*D_];                        // 2 MB
__device__ float g_ffh[R_*FF_];                     // 8 MB
__device__ float g_ff[R_*D_];                       // 2 MB
__device__ float g_wqkvT[QKV_*D_];                  // [1536][256]
__device__ float g_WpT[D_*H_*HS_];                  // [256][512]
__device__ float g_W1T[FF_*D_];                     // [1024][256]
__device__ float g_W2T[D_*FF_];                     // [256][1024]
__device__ float g_vT[(long)B_*H_*HS_*N_];          // [b][h*64+o][m]  4 MB
__device__ float g_part[2*R_*QKV_];                 // 25 MB split-K partials

// ---------------------------------------------------------------------------
// Repack Wq (scaled by 1/sqrt(HS)), Wk[:, :D], Wv into TRANSPOSED [1536][256]
// ---------------------------------------------------------------------------
__global__ void repack_wqkvT(const float* __restrict__ Wq,
                             const float* __restrict__ Wk,
                             const float* __restrict__ Wv,
                             float* __restrict__ out)
{
    int idx = blockIdx.x * blockDim.x + threadIdx.x;   // idx = j*256 + i
    if (idx >= D_ * QKV_) return;
    int j = idx / D_;        // output column of fused proj (0..1535)
    int i = idx % D_;        // input feature (0..255)
    float v;
    if (j < 512) {
        int h = j >> 6, o = j & 63;
        v = Wq[(h*D_ + i)*HS_ + o] * 0.125f;               // 1/sqrt(64)
    } else if (j < 1024) {
        int jj = j - 512; int h = jj >> 6, o = jj & 63;
        v = Wk[(h*(D_+E_) + i)*HS_ + o];
    } else {
        int jj = j - 1024; int h = jj >> 6, o = jj & 63;
        v = Wv[(h*D_ + i)*HS_ + o];
    }
    out[idx] = v;
}

// ---------------------------------------------------------------------------
// Generic tiled transpose: in[Rr][Cc] -> out[Cc][Rr]. Rr, Cc multiples of 32.
// ---------------------------------------------------------------------------
__global__ void transpose_k(const float* __restrict__ in, float* __restrict__ out,
                            int Rr, int Cc)
{
    __shared__ float tile[32][33];
    int x = blockIdx.x*32 + threadIdx.x;
    int y0 = blockIdx.y*32;
#pragma unroll
    for (int j = 0; j < 32; j += 8)
        tile[threadIdx.y + j][threadIdx.x] = in[(long)(y0 + threadIdx.y + j)*Cc + x];
    __syncthreads();
    int ox = y0 + threadIdx.x;
    int oy0 = blockIdx.x*32;
#pragma unroll
    for (int j = 0; j < 32; j += 8)
        out[(long)(oy0 + threadIdx.y + j)*Rr + ox] = tile[threadIdx.x][threadIdx.y + j];
}

// ---------------------------------------------------------------------------
// vT[b][c][m] = qkv[b*1024 + m][1024 + c]   (c = h*64+o, m = token)
// ---------------------------------------------------------------------------
__global__ void vt_kernel(const float* __restrict__ qkv, float* __restrict__ vT)
{
    __shared__ float tile[32][33];
    int b  = blockIdx.z;
    int c0 = blockIdx.x*32;
    int m0 = blockIdx.y*32;
#pragma unroll
    for (int j = 0; j < 32; j += 8)
        tile[threadIdx.y + j][threadIdx.x] =
            qkv[(long)(b*N_ + m0 + threadIdx.y + j)*QKV_ + 1024 + c0 + threadIdx.x];
    __syncthreads();
#pragma unroll
    for (int j = 0; j < 32; j += 8)
        vT[(long)(b*512 + c0 + threadIdx.y + j)*N_ + m0 + threadIdx.x] =
            tile[threadIdx.x][threadIdx.y + j];
}

// ---------------------------------------------------------------------------
// Deterministic slab reduction: out[i] = sum_j part[i + j*slab4] (float4 units)
// ---------------------------------------------------------------------------
__global__ void reduce_add(const float* __restrict__ part, float* __restrict__ out,
                           int n4, int nslab, long slab4)
{
    int i = blockIdx.x * blockDim.x + threadIdx.x;
    if (i >= n4) return;
    const float4* pp = (const float4*)part;
    float4 s = pp[i];
    for (int j = 1; j < nslab; ++j) {
        float4 v = pp[i + (long)j*slab4];
        s.x += v.x; s.y += v.y; s.z += v.z; s.w += v.w;
    }
    ((float4*)out)[i] = s;
}

// ---------------------------------------------------------------------------
// tf32 helpers / PTX wrappers
// ---------------------------------------------------------------------------
__device__ __forceinline__ float f2tf32(float x)
{
    unsigned r;
    asm("cvt.rna.tf32.f32 %0, %1;" : "=r"(r) : "f"(x));
    return __uint_as_float(r);
}

__device__ __forceinline__ void mma_tf32(float* c, const unsigned* a, const unsigned* b)
{
    asm volatile("mma.sync.aligned.m16n8k8.row.col.f32.tf32.tf32.f32 "
                 "{%0,%1,%2,%3},{%4,%5,%6,%7},{%8,%9},{%0,%1,%2,%3};"
                 : "+f"(c[0]), "+f"(c[1]), "+f"(c[2]), "+f"(c[3])
                 : "r"(a[0]), "r"(a[1]), "r"(a[2]), "r"(a[3]), "r"(b[0]), "r"(b[1]));
}

// ---------------------------------------------------------------------------
// Tensor-core GEMM (tf32 mma.sync m16n8k8, single pass), fp32 I/O.
//   C[m,n] = sum_k A[m,k]*B[k,n].
//   A: K contiguous, row stride as_m.      (optional: A := relu(A + a_bias[k]))
//   B: K contiguous (pre-transposed), "row" = n, row stride bs_n.
//   Batch z = (bo*inner + bi)*ksplit + ks. Split-K chunk ks shifts A/B/bias
//   by ks*K and C by ks*c_slab (partial slabs reduced by reduce_add).
//   All M,N,K exact multiples of tiles. BK=32. 8 warps (WM*WN==8).
//   smem row stride LD=36 floats: fragment LDS banks (4g+c)%32, conflict-free.
//   Single-stage static smem; next gmem tile prefetched into registers
//   between the two syncs so loads overlap the mma phase.
// ---------------------------------------------------------------------------
template<int BM, int BN, int WM, int WN>
__global__ __launch_bounds__(256)
void mgemm(const float* __restrict__ A, const float* __restrict__ Bm,
           const float* __restrict__ a_bias, float* __restrict__ C,
           int K,
           long as_m, long a_bso, long a_bsi,
           long bs_n, long b_bso, long b_bsi,
           long cs_m, long c_bso, long c_bsi,
           int inner, int ksplit, long c_slab)
{
    const int BK  = 32;
    const int LD  = 36;                  // 144B rows: frag LDS conflict-free
    const int NRA = BM/32;               // float4 per thread for A tile
    const int NRB = BN/32;
    const int WTM = BM/WM;
    const int WTN = BN/WN;
    const int FM  = WTM/16;
    const int FN  = WTN/8;

    __shared__ float4 smbuf[(BM + BN)*LD/4];
    float* sA = (float*)smbuf;
    float* sB = sA + BM*LD;

    const int t    = threadIdx.x;
    const int warp = t >> 5;
    const int lane = t & 31;
    const int wm   = warp / WN;
    const int wn   = warp % WN;

    const int  ks = blockIdx.z % ksplit;
    const long zz = blockIdx.z / ksplit;
    const long bo = zz / inner;
    const long bi = zz % inner;
    const long m0 = (long)blockIdx.y * BM;
    const long n0 = (long)blockIdx.x * BN;

    const float* Ab = A  + bo*a_bso + bi*a_bsi + m0*as_m + (long)ks*K;
    const float* Bb = Bm + bo*b_bso + bi*b_bsi + n0*bs_n + (long)ks*K;
    const float* bias = a_bias ? (a_bias + (long)ks*K) : a_bias;

    const int g = lane >> 2;           // fragment row group 0..7
    const int cc = lane & 3;           // fragment k lane 0..3

    float acc[FM][FN][4];
#pragma unroll
    for (int i = 0; i < FM; ++i)
#pragma unroll
        for (int j = 0; j < FN; ++j)
#pragma unroll
            for (int r = 0; r < 4; ++r) acc[i][j][r] = 0.f;

    float4 ra[NRA], rb[NRB];

    // ---- prologue: load tile 0 into registers ----
#pragma unroll
    for (int i = 0; i < NRA; ++i) {
        int f = t + i*256, row = f >> 3, c4 = (f & 7)*4;
        float4 v = *(const float4*)(Ab + (long)row*as_m + c4);
        if (bias) {
            float4 bb = *(const float4*)(bias + c4);
            v.x = fmaxf(v.x + bb.x, 0.f); v.y = fmaxf(v.y + bb.y, 0.f);
            v.z = fmaxf(v.z + bb.z, 0.f); v.w = fmaxf(v.w + bb.w, 0.f);
        }
        ra[i] = v;
    }
#pragma unroll
    for (int i = 0; i < NRB; ++i) {
        int f = t + i*256, row = f >> 3, c4 = (f & 7)*4;
        rb[i] = *(const float4*)(Bb + (long)row*bs_n + c4);
    }

    const int iters = K / BK;
#pragma unroll 1
    for (int it = 0; it < iters; ++it) {
        // ---- store register tile -> smem (tf32 round) ----
#pragma unroll
        for (int i = 0; i < NRA; ++i) {
            int f = t + i*256, row = f >> 3, c4 = (f & 7)*4;
            float4 w;
            w.x = f2tf32(ra[i].x); w.y = f2tf32(ra[i].y);
            w.z = f2tf32(ra[i].z); w.w = f2tf32(ra[i].w);
            *(float4*)(sA + row*LD + c4) = w;
        }
#pragma unroll
        for (int i = 0; i < NRB; ++i) {
            int f = t + i*256, row = f >> 3, c4 = (f & 7)*4;
            float4 w;
            w.x = f2tf32(rb[i].x); w.y = f2tf32(rb[i].y);
            w.z = f2tf32(rb[i].z); w.w = f2tf32(rb[i].w);
            *(float4*)(sB + row*LD + c4) = w;
        }
        __syncthreads();

        // ---- prefetch next tile into registers (overlaps mma phase) ----
        if (it + 1 < iters) {
            int k0 = (it + 1) * BK;
#pragma unroll
            for (int i = 0; i < NRA; ++i) {
                int f = t + i*256, row = f >> 3, c4 = (f & 7)*4;
                float4 v = *(const float4*)(Ab + (long)row*as_m + k0 + c4);
                if (bias) {
                    float4 bb = *(const float4*)(bias + k0 + c4);
                    v.x = fmaxf(v.x + bb.x, 0.f); v.y = fmaxf(v.y + bb.y, 0.f);
                    v.z = fmaxf(v.z + bb.z, 0.f); v.w = fmaxf(v.w + bb.w, 0.f);
                }
                ra[i] = v;
            }
#pragma unroll
            for (int i = 0; i < NRB; ++i) {
                int f = t + i*256, row = f >> 3, c4 = (f & 7)*4;
                rb[i] = *(const float4*)(Bb + (long)row*bs_n + k0 + c4);
            }
        }

        // ---- compute: 4 k-slices of 8 (tf32 m16n8k8) ----
#pragma unroll
        for (int ks8 = 0; ks8 < 4; ++ks8) {
            const int kb = ks8*8;
            unsigned af[FM][4], bf[FN][2];
#pragma unroll
            for (int fm = 0; fm < FM; ++fm) {
                const float* pa = sA + (wm*WTM + fm*16 + g)*LD + kb + cc;
                af[fm][0] = __float_as_uint(pa[0]);
                af[fm][1] = __float_as_uint(pa[8*LD]);
                af[fm][2] = __float_as_uint(pa[4]);
                af[fm][3] = __float_as_uint(pa[8*LD + 4]);
            }
#pragma unroll
            for (int fn = 0; fn < FN; ++fn) {
                const float* pb = sB + (wn*WTN + fn*8 + g)*LD + kb + cc;
                bf[fn][0] = __float_as_uint(pb[0]);
                bf[fn][1] = __float_as_uint(pb[4]);
            }
#pragma unroll
            for (int fm = 0; fm < FM; ++fm)
#pragma unroll
                for (int fn = 0; fn < FN; ++fn)
                    mma_tf32(acc[fm][fn], af[fm], bf[fn]);
        }
        __syncthreads();
    }

    // ---- epilogue ----
    const int tig = lane & 3;
    float* Cb = C + bo*c_bso + bi*c_bsi + (long)ks*c_slab;
#pragma unroll
    for (int fm = 0; fm < FM; ++fm) {
#pragma unroll
        for (int fn = 0; fn < FN; ++fn) {
            float* p = Cb + (m0 + wm*WTM + fm*16 + g)*cs_m
                          + n0 + wn*WTN + fn*8 + 2*tig;
            float2 v0; v0.x = acc[fm][fn][0]; v0.y = acc[fm][fn][1];
            float2 v1; v1.x = acc[fm][fn][2]; v1.y = acc[fm][fn][3];
            *(float2*)p            = v0;
            *(float2*)(p + 8*cs_m) = v1;
        }
    }
}

// ---------------------------------------------------------------------------
// Edge-conditioned logits + softmax, fused. One CTA per (b, n). 256 threads.
//   logits[b,h,n,m] += sum_e qe[b,n,h,e] * edge[b,n,m,e]  ; softmax over m.
// ---------------------------------------------------------------------------
#define EDGE_SMEM_BYTES ((8192 + 256*17*4 + 128*4) * 4)   // 104448

__global__ __launch_bounds__(256)
void edge_softmax_kernel(const float* __restrict__ edge,
                         const float* __restrict__ qe,
                         float* __restrict__ logits)
{
    extern __shared__ float smem[];
    float*  s_logits = smem;                       // 8192 floats
    float4* s_edge4  = (float4*)(smem + 8192);     // 256*17 float4
    float4* s_qe4    = s_edge4 + 256*17;           // 128 float4

    const int t  = threadIdx.x;
    const int bn = blockIdx.x;
    const int b  = bn >> 10;
    const int n  = bn & 1023;

    if (t < 128) s_qe4[t] = ((const float4*)(qe + (long)bn*512))[t];

    const float* lg = logits + ((long)(b*H_)*N_ + n) * N_;
#pragma unroll
    for (int h = 0; h < H_; ++h) {
        const float4* src = (const float4*)(lg + (long)h*N_*N_);
        ((float4*)(s_logits + h*N_))[t] = src[t];
    }
    __syncthreads();

    const float4* eg = (const float4*)(edge + ((long)bn << 16));
    const int tx = t & 63;            // m lane
    const int hg = t >> 6;            // head group 0..3 -> heads {2hg, 2hg+1}

    for (int mt = 0; mt < 4; ++mt) {
#pragma unroll 16
        for (int i = 0; i < 16; ++i) {
            int f   = t + i*256;
            int row = f >> 4, c = f & 15;
            s_edge4[row*17 + c] = eg[(mt*256 + row)*16 + c];
        }
        __syncthreads();

        float acc[4][2];
#pragma unroll
        for (int i = 0; i < 4; ++i) {
            acc[i][0] = 0.f; acc[i][1] = 0.f;
        }

#pragma unroll
        for (int e4 = 0; e4 < 16; ++e4) {
            float4 ev[4], qv[2];
#pragma unroll
            for (int i = 0; i < 4; ++i) ev[i] = s_edge4[(tx + i*64)*17 + e4];
            qv[0] = s_qe4[(hg*2 + 0)*16 + e4];
            qv[1] = s_qe4[(hg*2 + 1)*16 + e4];
#pragma unroll
            for (int i = 0; i < 4; ++i) {
                acc[i][0] += ev[i].x*qv[0].x + ev[i].y*qv[0].y
                           + ev[i].z*qv[0].z + ev[i].w*qv[0].w;
                acc[i][1] += ev[i].x*qv[1].x + ev[i].y*qv[1].y
                           + ev[i].z*qv[1].z + ev[i].w*qv[1].w;
            }
        }
#pragma unroll
        for (int j = 0; j < 2; ++j)
#pragma unroll
            for (int i = 0; i < 4; ++i)
                s_logits[(hg*2 + j)*N_ + mt*256 + i*64 + tx] += acc[i][j];
        __syncthreads();
    }

    const int warp = t >> 5, lane = t & 31;
    for (int h = warp; h < H_; h += 8) {
        const float* row = s_logits + h*N_;
        float mx = -1e30f;
#pragma unroll
        for (int i = 0; i < 32; ++i) mx = fmaxf(mx, row[lane + i*32]);
#pragma unroll
        for (int o = 16; o; o >>= 1) mx = fmaxf(mx, __shfl_xor_sync(~0u, mx, o));
        float vals[32];
        float sum = 0.f;
#pragma unroll
        for (int i = 0; i < 32; ++i) {
            vals[i] = __expf(row[lane + i*32] - mx);
            sum += vals[i];
        }
#pragma unroll
        for (int o = 16; o; o >>= 1) sum += __shfl_xor_sync(~0u, sum, o);
        const float inv = 1.f / sum;
        float* out = logits + ((long)(b*H_ + h)*N_ + n) * N_;
#pragma unroll
        for (int i = 0; i < 32; ++i) out[lane + i*32] = vals[i] * inv;
    }
}

// ---------------------------------------------------------------------------
// LayerNorm over last dim (256), fused residual + residual-bias.
// ---------------------------------------------------------------------------
__global__ __launch_bounds__(256)
void ln_kernel(const float* __restrict__ a, const float* __restrict__ r,
               const float* __restrict__ rb,
               const float* __restrict__ gam, const float* __restrict__ bet,
               float* __restrict__ out)
{
    const int warp = threadIdx.x >> 5, lane = threadIdx.x & 31;
    const long row = (long)blockIdx.x * 8 + warp;
    const float4* pa = (const float4*)(a + row*D_);
    const float4* pr = (const float4*)(r + row*D_);
    const float4 rb0 = ((const float4*)rb)[lane], rb1 = ((const float4*)rb)[lane + 32];
    float4 v0 = pa[lane], v1 = pa[lane + 32];
    const float4 q0 = pr[lane], q1 = pr[lane + 32];
    v0.x += q0.x + rb0.x; v0.y += q0.y + rb0.y; v0.z += q0.z + rb0.z; v0.w += q0.w + rb0.w;
    v1.x += q1.x + rb1.x; v1.y += q1.y + rb1.y; v1.z += q1.z + rb1.z; v1.w += q1.w + rb1.w;

    float s = v0.x + v0.y + v0.z + v0.w + v1.x + v1.y + v1.z + v1.w;
#pragma unroll
    for (int o = 16; o; o >>= 1) s += __shfl_xor_sync(~0u, s, o);
    const float mu = s * (1.f / 256.f);

    float4 d0, d1;
    d0.x = v0.x - mu; d0.y = v0.y - mu; d0.z = v0.z - mu; d0.w = v0.w - mu;
    d1.x = v1.x - mu; d1.y = v1.y - mu; d1.z = v1.z - mu; d1.w = v1.w - mu;
    float var = d0.x*d0.x + d0.y*d0.y + d0.z*d0.z + d0.w*d0.w
              + d1.x*d1.x + d1.y*d1.y + d1.z*d1.z + d1.w*d1.w;
#pragma unroll
    for (int o = 16; o; o >>= 1) var += __shfl_xor_sync(~0u, var, o);
    const float rs = rsqrtf(var * (1.f / 256.f) + 1e-6f);

    const float4 g0 = ((const float4*)gam)[lane], g1 = ((const float4*)gam)[lane + 32];
    const float4 bb0 = ((const float4*)bet)[lane], bb1 = ((const float4*)bet)[lane + 32];
    float4 o0, o1;
    o0.x = d0.x*rs*g0.x + bb0.x; o0.y = d0.y*rs*g0.y + bb0.y;
    o0.z = d0.z*rs*g0.z + bb0.z; o0.w = d0.w*rs*g0.w + bb0.w;
    o1.x = d1.x*rs*g1.x + bb1.x; o1.y = d1.y*rs*g1.y + bb1.y;
    o1.z = d1.z*rs*g1.z + bb1.z; o1.w = d1.w*rs*g1.w + bb1.w;
    ((float4*)(out + row*D_))[lane]      = o0;
    ((float4*)(out + row*D_))[lane + 32] = o1;
}

// ---------------------------------------------------------------------------
// Host launch (graph-capturable)
// ---------------------------------------------------------------------------
extern "C" void kernel_launch(void* const* d_in, const int* in_sizes, int n_in,
                              void* d_out, int out_size)
{
    const float* node = (const float*)d_in[0];
    const float* edge = (const float*)d_in[1];
    const float* Wq   = (const float*)d_in[2];
    const float* Wk   = (const float*)d_in[3];
    const float* Wv   = (const float*)d_in[4];
    const float* Wp   = (const float*)d_in[5];
    const float* bp   = (const float*)d_in[6];
    const float* ln1g = (const float*)d_in[7];
    const float* ln1b = (const float*)d_in[8];
    const float* W1   = (const float*)d_in[9];
    const float* b1   = (const float*)d_in[10];
    const float* W2   = (const float*)d_in[11];
    const float* b2   = (const float*)d_in[12];
    const float* ln2g = (const float*)d_in[13];
    const float* ln2b = (const float*)d_in[14];

    float *qkv, *qe, *logits, *mo, *mha, *x, *ffh, *ff;
    float *wqkvT, *WpT, *W1T, *W2T, *vT, *part;
    cudaGetSymbolAddress((void**)&qkv,    g_qkv);
    cudaGetSymbolAddress((void**)&qe,     g_qe);
    cudaGetSymbolAddress((void**)&logits, g_logits);
    cudaGetSymbolAddress((void**)&mo,     g_mo);
    cudaGetSymbolAddress((void**)&mha,    g_mha);
    cudaGetSymbolAddress((void**)&x,      g_x);
    cudaGetSymbolAddress((void**)&ffh,    g_ffh);
    cudaGetSymbolAddress((void**)&ff,     g_ff);
    cudaGetSymbolAddress((void**)&wqkvT,  g_wqkvT);
    cudaGetSymbolAddress((void**)&WpT,    g_WpT);
    cudaGetSymbolAddress((void**)&W1T,    g_W1T);
    cudaGetSymbolAddress((void**)&W2T,    g_W2T);
    cudaGetSymbolAddress((void**)&vT,     g_vT);
    cudaGetSymbolAddress((void**)&part,   g_part);

    cudaFuncSetAttribute(edge_softmax_kernel,
                         cudaFuncAttributeMaxDynamicSharedMemorySize, EDGE_SMEM_BYTES);

    // 0) weight repacks (transposed layouts; all B operands become k-contiguous)
    repack_wqkvT<<<(D_*QKV_ + 255)/256, 256>>>(Wq, Wk, Wv, wqkvT);
    transpose_k<<<dim3(D_/32, 512/32),  dim3(32,8)>>>(Wp, WpT, 512, D_);
    transpose_k<<<dim3(FF_/32, D_/32),  dim3(32,8)>>>(W1, W1T, D_, FF_);
    transpose_k<<<dim3(D_/32, FF_/32),  dim3(32,8)>>>(W2, W2T, FF_, D_);

    // 1) fused QKV projection split-K2: qkv = node @ wqkvT^T  (768 CTAs)
    mgemm<128,64,4,2><<<dim3(QKV_/64, R_/128, 2), 256>>>(
        node, wqkvT, (const float*)0, part, D_/2,
        D_, 0, 0,
        D_, 0, 0,
        QKV_, 0, 0, 1, 2, (long)R_*QKV_);
    reduce_add<<<(R_*QKV_/4 + 255)/256, 256>>>(part, qkv, R_*QKV_/4, 2, (long)R_*QKV_/4);

    // 1b) v transpose for AV's B operand
    vt_kernel<<<dim3(512/32, N_/32, B_), dim3(32,8)>>>(qkv, vT);

    // 2) qe[r][h*64+e] = q_h[r,:] @ WkE_h^T   (z = h; 256 CTAs)
    mgemm<64,64,2,4><<<dim3(1, R_/64, H_), 256>>>(
        qkv, Wk + (long)D_*HS_, (const float*)0, qe, HS_,
        QKV_, 64, 0,
        HS_, (long)(D_+E_)*HS_, 0,
        (long)H_*E_, 64, 0, 1, 1, 0);

    // 3) QK^T logits (z = b*8+h; 2048 CTAs)
    mgemm<128,64,4,2><<<dim3(N_/64, N_/128, B_*H_), 256>>>(
        qkv, qkv + 512, (const float*)0, logits, HS_,
        QKV_, (long)N_*QKV_, 64,
        QKV_, (long)N_*QKV_, 64,
        N_, (long)H_*N_*N_, (long)N_*N_, H_, 1, 0);

    // 4) edge logits + softmax (streams 536 MB; in-place probs)
    edge_softmax_kernel<<<R_, 256, EDGE_SMEM_BYTES>>>(edge, qe, logits);

    // 5) AV split-K4: part[ks] = attn[.., chunk] @ vT[chunk]  (1024 CTAs)
    mgemm<64,64,2,4><<<dim3(1, N_/64, B_*H_*4), 256>>>(
        logits, vT, (const float*)0, part, N_/4,
        N_, (long)H_*N_*N_, (long)N_*N_,
        N_, (long)512*N_, (long)64*N_,
        (long)H_*HS_, (long)N_*H_*HS_, 64, H_, 4, (long)R_*512);
    reduce_add<<<(R_*512/4 + 255)/256, 256>>>(part, mo, R_*512/4, 4, (long)R_*512/4);

    // 6) output projection split-K2: part[ks] = mo[..,ks] @ WpT[ks]  (256 CTAs)
    mgemm<64,64,2,4><<<dim3(D_/64, R_/64, 2), 256>>>(
        mo, WpT, (const float*)0, part, (H_*HS_)/2,
        (long)H_*HS_, 0, 0,
        (long)H_*HS_, 0, 0,
        D_, 0, 0, 1, 2, (long)R_*D_);
    reduce_add<<<(R_*D_/4 + 255)/256, 256>>>(part, mha, R_*D_/4, 2, (long)R_*D_/4);

    // 7) x = LN1(node + mha + bp)
    ln_kernel<<<R_/8, 256>>>(node, mha, bp, ln1g, ln1b, x);

    // 8) FFN hidden split-K2: ffh = x @ W1  (512 CTAs; b1+relu fused into step 9)
    mgemm<128,64,4,2><<<dim3(FF_/64, R_/128, 2), 256>>>(
        x, W1T, (const float*)0, part, D_/2,
        D_, 0, 0,
        D_, 0, 0,
        FF_, 0, 0, 1, 2, (long)R_*FF_);
    reduce_add<<<(R_*FF_/4 + 255)/256, 256>>>(part, ffh, R_*FF_/4, 2, (long)R_*FF_/4);

    // 9) FFN out split-K4: part[ks] = relu(ffh+b1)[ks] @ W2T[ks]  (512 CTAs)
    mgemm<64,64,2,4><<<dim3(D_/64, R_/64, 4), 256>>>(
        ffh, W2T, b1, part, FF_/4,
        FF_, 0, 0,
        FF_, 0, 0,
        D_, 0, 0, 1, 4, (long)R_*D_);
    reduce_add<<<(R_*D_/4 + 255)/256, 256>>>(part, ff, R_*D_/4, 4, (long)R_*D_/4);

    // 10) out = LN2(x + ff + b2)
    ln_kernel<<<R_/8, 256>>>(x, ff, b2, ln2g, ln2b, (float*)d_out);
}

// round 14
// speedup vs baseline: 1.0595x; 1.0273x over previous
#include <cuda_runtime.h>
#include <cuda_bf16.h>

// Shapes (compile-time; problem is fixed-shape)
#define B_   2
#define N_   1024
#define D_   256
#define E_   64
#define H_   8
#define HS_  64
#define FF_  1024
#define R_   (B_*N_)        // 2048 token rows
#define QKV_ (3*H_*HS_)     // 1536

// ---------------------------------------------------------------------------
// Scratch (device globals; no runtime allocation allowed)
// ---------------------------------------------------------------------------
__device__ float g_qkv[R_*QKV_];                    // q | kn | v   (12 MB)
__device__ float g_qe[R_*H_*E_];                    // 4 MB
__device__ float g_logits[(long)B_*H_*N_*N_];       // 64 MB (reused as attn probs)
__device__ float g_mo[R_*H_*HS_];                   // 4 MB
__device__ float g_mha[R_*D_];                      // 2 MB
__device__ float g_x[R_*D_];                        // 2 MB
__device__ float g_ffh[R_*FF_];                     // 8 MB
__device__ float g_ff[R_*D_];                       // 2 MB
__device__ float g_wqkvT[QKV_*D_];                  // [1536][256]
__device__ float g_WpT[D_*H_*HS_];                  // [256][512]
__device__ float g_W1T[FF_*D_];                     // [1024][256]
__device__ float g_W2T[D_*FF_];                     // [256][1024]
__device__ float g_vT[(long)B_*H_*HS_*N_];          // [b][h*64+o][m]  4 MB
__device__ float g_part[2*R_*QKV_];                 // 25 MB split-K partials

// ---------------------------------------------------------------------------
// Repack Wq (scaled by 1/sqrt(HS)), Wk[:, :D], Wv into TRANSPOSED [1536][256]
// ---------------------------------------------------------------------------
__global__ void repack_wqkvT(const float* __restrict__ Wq,
                             const float* __restrict__ Wk,
                             const float* __restrict__ Wv,
                             float* __restrict__ out)
{
    int idx = blockIdx.x * blockDim.x + threadIdx.x;   // idx = j*256 + i
    if (idx >= D_ * QKV_) return;
    int j = idx / D_;        // output column of fused proj (0..1535)
    int i = idx % D_;        // input feature (0..255)
    float v;
    if (j < 512) {
        int h = j >> 6, o = j & 63;
        v = Wq[(h*D_ + i)*HS_ + o] * 0.125f;               // 1/sqrt(64)
    } else if (j < 1024) {
        int jj = j - 512; int h = jj >> 6, o = jj & 63;
        v = Wk[(h*(D_+E_) + i)*HS_ + o];
    } else {
        int jj = j - 1024; int h = jj >> 6, o = jj & 63;
        v = Wv[(h*D_ + i)*HS_ + o];
    }
    out[idx] = v;
}

// ---------------------------------------------------------------------------
// Generic tiled transpose: in[Rr][Cc] -> out[Cc][Rr]. Rr, Cc multiples of 32.
// ---------------------------------------------------------------------------
__global__ void transpose_k(const float* __restrict__ in, float* __restrict__ out,
                            int Rr, int Cc)
{
    __shared__ float tile[32][33];
    int x = blockIdx.x*32 + threadIdx.x;
    int y0 = blockIdx.y*32;
#pragma unroll
    for (int j = 0; j < 32; j += 8)
        tile[threadIdx.y + j][threadIdx.x] = in[(long)(y0 + threadIdx.y + j)*Cc + x];
    __syncthreads();
    int ox = y0 + threadIdx.x;
    int oy0 = blockIdx.x*32;
#pragma unroll
    for (int j = 0; j < 32; j += 8)
        out[(long)(oy0 + threadIdx.y + j)*Rr + ox] = tile[threadIdx.x][threadIdx.y + j];
}

// ---------------------------------------------------------------------------
// vT[b][c][m] = qkv[b*1024 + m][1024 + c]   (c = h*64+o, m = token)
// ---------------------------------------------------------------------------
__global__ void vt_kernel(const float* __restrict__ qkv, float* __restrict__ vT)
{
    __shared__ float tile[32][33];
    int b  = blockIdx.z;
    int c0 = blockIdx.x*32;
    int m0 = blockIdx.y*32;
#pragma unroll
    for (int j = 0; j < 32; j += 8)
        tile[threadIdx.y + j][threadIdx.x] =
            qkv[(long)(b*N_ + m0 + threadIdx.y + j)*QKV_ + 1024 + c0 + threadIdx.x];
    __syncthreads();
#pragma unroll
    for (int j = 0; j < 32; j += 8)
        vT[(long)(b*512 + c0 + threadIdx.y + j)*N_ + m0 + threadIdx.x] =
            tile[threadIdx.x][threadIdx.y + j];
}

// ---------------------------------------------------------------------------
// Deterministic slab reduction: out[i] = sum_j part[i + j*slab4] (float4 units)
// ---------------------------------------------------------------------------
__global__ void reduce_add(const float* __restrict__ part, float* __restrict__ out,
                           int n4, int nslab, long slab4)
{
    int i = blockIdx.x * blockDim.x + threadIdx.x;
    if (i >= n4) return;
    const float4* pp = (const float4*)part;
    float4 s = pp[i];
    for (int j = 1; j < nslab; ++j) {
        float4 v = pp[i + (long)j*slab4];
        s.x += v.x; s.y += v.y; s.z += v.z; s.w += v.w;
    }
    ((float4*)out)[i] = s;
}

// ---------------------------------------------------------------------------
// tf32 helpers / PTX wrappers
// ---------------------------------------------------------------------------
__device__ __forceinline__ float f2tf32(float x)
{
    unsigned r;
    asm("cvt.rna.tf32.f32 %0, %1;" : "=r"(r) : "f"(x));
    return __uint_as_float(r);
}

__device__ __forceinline__ void mma_tf32(float* c, const unsigned* a, const unsigned* b)
{
    asm volatile("mma.sync.aligned.m16n8k8.row.col.f32.tf32.tf32.f32 "
                 "{%0,%1,%2,%3},{%4,%5,%6,%7},{%8,%9},{%0,%1,%2,%3};"
                 : "+f"(c[0]), "+f"(c[1]), "+f"(c[2]), "+f"(c[3])
                 : "r"(a[0]), "r"(a[1]), "r"(a[2]), "r"(a[3]), "r"(b[0]), "r"(b[1]));
}

// ---------------------------------------------------------------------------
// Tensor-core GEMM (tf32 mma.sync m16n8k8, single pass), fp32 I/O.
//   C[m,n] = sum_k A[m,k]*B[k,n].
//   A: K contiguous, row stride as_m.      (optional: A := relu(A + a_bias[k]))
//   B: K contiguous (pre-transposed), "row" = n, row stride bs_n.
//   Batch z = (bo*inner + bi)*ksplit + ks. Split-K chunk ks shifts A/B/bias
//   by ks*K and C by ks*c_slab (partial slabs reduced by reduce_add).
//   All M,N,K exact multiples of tiles. BK=32. 8 warps (WM*WN==8).
//   smem row stride LD=36 floats: fragment LDS banks (4g+c)%32, conflict-free.
//   Single-stage static smem; next gmem tile prefetched into registers
//   between the two syncs so loads overlap the mma phase.
// ---------------------------------------------------------------------------
template<int BM, int BN, int WM, int WN>
__global__ __launch_bounds__(256)
void mgemm(const float* __restrict__ A, const float* __restrict__ Bm,
           const float* __restrict__ a_bias, float* __restrict__ C,
           int K,
           long as_m, long a_bso, long a_bsi,
           long bs_n, long b_bso, long b_bsi,
           long cs_m, long c_bso, long c_bsi,
           int inner, int ksplit, long c_slab)
{
    const int BK  = 32;
    const int LD  = 36;                  // 144B rows: frag LDS conflict-free
    const int NRA = BM/32;               // float4 per thread for A tile
    const int NRB = BN/32;
    const int WTM = BM/WM;
    const int WTN = BN/WN;
    const int FM  = WTM/16;
    const int FN  = WTN/8;

    __shared__ float4 smbuf[(BM + BN)*LD/4];
    float* sA = (float*)smbuf;
    float* sB = sA + BM*LD;

    const int t    = threadIdx.x;
    const int warp = t >> 5;
    const int lane = t & 31;
    const int wm   = warp / WN;
    const int wn   = warp % WN;

    const int  ks = blockIdx.z % ksplit;
    const long zz = blockIdx.z / ksplit;
    const long bo = zz / inner;
    const long bi = zz % inner;
    const long m0 = (long)blockIdx.y * BM;
    const long n0 = (long)blockIdx.x * BN;

    const float* Ab = A  + bo*a_bso + bi*a_bsi + m0*as_m + (long)ks*K;
    const float* Bb = Bm + bo*b_bso + bi*b_bsi + n0*bs_n + (long)ks*K;
    const float* bias = a_bias ? (a_bias + (long)ks*K) : a_bias;

    const int g = lane >> 2;           // fragment row group 0..7
    const int cc = lane & 3;           // fragment k lane 0..3

    float acc[FM][FN][4];
#pragma unroll
    for (int i = 0; i < FM; ++i)
#pragma unroll
        for (int j = 0; j < FN; ++j)
#pragma unroll
            for (int r = 0; r < 4; ++r) acc[i][j][r] = 0.f;

    float4 ra[NRA], rb[NRB];

    // ---- prologue: load tile 0 into registers ----
#pragma unroll
    for (int i = 0; i < NRA; ++i) {
        int f = t + i*256, row = f >> 3, c4 = (f & 7)*4;
        float4 v = *(const float4*)(Ab + (long)row*as_m + c4);
        if (bias) {
            float4 bb = *(const float4*)(bias + c4);
            v.x = fmaxf(v.x + bb.x, 0.f); v.y = fmaxf(v.y + bb.y, 0.f);
            v.z = fmaxf(v.z + bb.z, 0.f); v.w = fmaxf(v.w + bb.w, 0.f);
        }
        ra[i] = v;
    }
#pragma unroll
    for (int i = 0; i < NRB; ++i) {
        int f = t + i*256, row = f >> 3, c4 = (f & 7)*4;
        rb[i] = *(const float4*)(Bb + (long)row*bs_n + c4);
    }

    const int iters = K / BK;
#pragma unroll 1
    for (int it = 0; it < iters; ++it) {
        // ---- store register tile -> smem (tf32 round) ----
#pragma unroll
        for (int i = 0; i < NRA; ++i) {
            int f = t + i*256, row = f >> 3, c4 = (f & 7)*4;
            float4 w;
            w.x = f2tf32(ra[i].x); w.y = f2tf32(ra[i].y);
            w.z = f2tf32(ra[i].z); w.w = f2tf32(ra[i].w);
            *(float4*)(sA + row*LD + c4) = w;
        }
#pragma unroll
        for (int i = 0; i < NRB; ++i) {
            int f = t + i*256, row = f >> 3, c4 = (f & 7)*4;
            float4 w;
            w.x = f2tf32(rb[i].x); w.y = f2tf32(rb[i].y);
            w.z = f2tf32(rb[i].z); w.w = f2tf32(rb[i].w);
            *(float4*)(sB + row*LD + c4) = w;
        }
        __syncthreads();

        // ---- prefetch next tile into registers (overlaps mma phase) ----
        if (it + 1 < iters) {
            int k0 = (it + 1) * BK;
#pragma unroll
            for (int i = 0; i < NRA; ++i) {
                int f = t + i*256, row = f >> 3, c4 = (f & 7)*4;
                float4 v = *(const float4*)(Ab + (long)row*as_m + k0 + c4);
                if (bias) {
                    float4 bb = *(const float4*)(bias + k0 + c4);
                    v.x = fmaxf(v.x + bb.x, 0.f); v.y = fmaxf(v.y + bb.y, 0.f);
                    v.z = fmaxf(v.z + bb.z, 0.f); v.w = fmaxf(v.w + bb.w, 0.f);
                }
                ra[i] = v;
            }
#pragma unroll
            for (int i = 0; i < NRB; ++i) {
                int f = t + i*256, row = f >> 3, c4 = (f & 7)*4;
                rb[i] = *(const float4*)(Bb + (long)row*bs_n + k0 + c4);
            }
        }

        // ---- compute: 4 k-slices of 8 (tf32 m16n8k8) ----
#pragma unroll
        for (int ks8 = 0; ks8 < 4; ++ks8) {
            const int kb = ks8*8;
            unsigned af[FM][4], bf[FN][2];
#pragma unroll
            for (int fm = 0; fm < FM; ++fm) {
                const float* pa = sA + (wm*WTM + fm*16 + g)*LD + kb + cc;
                af[fm][0] = __float_as_uint(pa[0]);
                af[fm][1] = __float_as_uint(pa[8*LD]);
                af[fm][2] = __float_as_uint(pa[4]);
                af[fm][3] = __float_as_uint(pa[8*LD + 4]);
            }
#pragma unroll
            for (int fn = 0; fn < FN; ++fn) {
                const float* pb = sB + (wn*WTN + fn*8 + g)*LD + kb + cc;
                bf[fn][0] = __float_as_uint(pb[0]);
                bf[fn][1] = __float_as_uint(pb[4]);
            }
#pragma unroll
            for (int fm = 0; fm < FM; ++fm)
#pragma unroll
                for (int fn = 0; fn < FN; ++fn)
                    mma_tf32(acc[fm][fn], af[fm], bf[fn]);
        }
        __syncthreads();
    }

    // ---- epilogue ----
    const int tig = lane & 3;
    float* Cb = C + bo*c_bso + bi*c_bsi + (long)ks*c_slab;
#pragma unroll
    for (int fm = 0; fm < FM; ++fm) {
#pragma unroll
        for (int fn = 0; fn < FN; ++fn) {
            float* p = Cb + (m0 + wm*WTM + fm*16 + g)*cs_m
                          + n0 + wn*WTN + fn*8 + 2*tig;
            float2 v0; v0.x = acc[fm][fn][0]; v0.y = acc[fm][fn][1];
            float2 v1; v1.x = acc[fm][fn][2]; v1.y = acc[fm][fn][3];
            *(float2*)p            = v0;
            *(float2*)(p + 8*cs_m) = v1;
        }
    }
}

// ---------------------------------------------------------------------------
// Edge-conditioned logits + softmax, fused. One CTA per (b, n). 256 threads.
//   logits[b,h,n,m] += sum_e qe[b,n,h,e] * edge[b,n,m,e]  ; softmax over m.
// Register-prefetch double buffering: tile mt+1 is loaded into registers
// while tile mt is computed from smem (removes the load->compute convoy).
// ---------------------------------------------------------------------------
#define EDGE_SMEM_BYTES ((8192 + 256*17*4 + 128*4) * 4)   // 104448

__global__ __launch_bounds__(256)
void edge_softmax_kernel(const float* __restrict__ edge,
                         const float* __restrict__ qe,
                         float* __restrict__ logits)
{
    extern __shared__ float smem[];
    float*  s_logits = smem;                       // 8192 floats
    float4* s_edge4  = (float4*)(smem + 8192);     // 256*17 float4
    float4* s_qe4    = s_edge4 + 256*17;           // 128 float4

    const int t  = threadIdx.x;
    const int bn = blockIdx.x;
    const int b  = bn >> 10;
    const int n  = bn & 1023;

    if (t < 128) s_qe4[t] = ((const float4*)(qe + (long)bn*512))[t];

    // init s_logits with QK logits (256 float4 per head, 1 per thread)
    const float* lg = logits + ((long)(b*H_)*N_ + n) * N_;
#pragma unroll
    for (int h = 0; h < H_; ++h) {
        const float4* src = (const float4*)(lg + (long)h*N_*N_);
        ((float4*)(s_logits + h*N_))[t] = src[t];
    }

    const float4* eg = (const float4*)(edge + ((long)bn << 16));
    const int tx = t & 63;            // m lane
    const int hg = t >> 6;            // head group 0..3 -> heads {2hg, 2hg+1}

    // prologue: tile 0 -> registers (flat index: eg[mt*4096 + f], f = row*16+c)
    float4 rg[16];
#pragma unroll
    for (int i = 0; i < 16; ++i) rg[i] = eg[t + i*256];

    __syncthreads();   // covers s_logits/qe init

    for (int mt = 0; mt < 4; ++mt) {
        // ---- store register tile -> smem (swizzled rows of 17 f4) ----
#pragma unroll
        for (int i = 0; i < 16; ++i) {
            int f = t + i*256;
            s_edge4[(f >> 4)*17 + (f & 15)] = rg[i];
        }
        __syncthreads();

        // ---- prefetch next tile into registers (overlaps compute) ----
        if (mt + 1 < 4) {
#pragma unroll
            for (int i = 0; i < 16; ++i)
                rg[i] = eg[(mt + 1)*4096 + t + i*256];
        }

        float acc[4][2];
#pragma unroll
        for (int i = 0; i < 4; ++i) {
            acc[i][0] = 0.f; acc[i][1] = 0.f;
        }

#pragma unroll
        for (int e4 = 0; e4 < 16; ++e4) {
            float4 ev[4], qv[2];
#pragma unroll
            for (int i = 0; i < 4; ++i) ev[i] = s_edge4[(tx + i*64)*17 + e4];
            qv[0] = s_qe4[(hg*2 + 0)*16 + e4];
            qv[1] = s_qe4[(hg*2 + 1)*16 + e4];
#pragma unroll
            for (int i = 0; i < 4; ++i) {
                acc[i][0] += ev[i].x*qv[0].x + ev[i].y*qv[0].y
                           + ev[i].z*qv[0].z + ev[i].w*qv[0].w;
                acc[i][1] += ev[i].x*qv[1].x + ev[i].y*qv[1].y
                           + ev[i].z*qv[1].z + ev[i].w*qv[1].w;
            }
        }
#pragma unroll
        for (int j = 0; j < 2; ++j)
#pragma unroll
            for (int i = 0; i < 4; ++i)
                s_logits[(hg*2 + j)*N_ + mt*256 + i*64 + tx] += acc[i][j];
        __syncthreads();
    }

    // softmax: one warp per head (8 warps, 8 heads)
    const int warp = t >> 5, lane = t & 31;
    for (int h = warp; h < H_; h += 8) {
        const float* row = s_logits + h*N_;
        float mx = -1e30f;
#pragma unroll
        for (int i = 0; i < 32; ++i) mx = fmaxf(mx, row[lane + i*32]);
#pragma unroll
        for (int o = 16; o; o >>= 1) mx = fmaxf(mx, __shfl_xor_sync(~0u, mx, o));
        float vals[32];
        float sum = 0.f;
#pragma unroll
        for (int i = 0; i < 32; ++i) {
            vals[i] = __expf(row[lane + i*32] - mx);
            sum += vals[i];
        }
#pragma unroll
        for (int o = 16; o; o >>= 1) sum += __shfl_xor_sync(~0u, sum, o);
        const float inv = 1.f / sum;
        float* out = logits + ((long)(b*H_ + h)*N_ + n) * N_;
#pragma unroll
        for (int i = 0; i < 32; ++i) out[lane + i*32] = vals[i] * inv;
    }
}

// ---------------------------------------------------------------------------
// LayerNorm over last dim (256), fused residual + residual-bias.
// ---------------------------------------------------------------------------
__global__ __launch_bounds__(256)
void ln_kernel(const float* __restrict__ a, const float* __restrict__ r,
               const float* __restrict__ rb,
               const float* __restrict__ gam, const float* __restrict__ bet,
               float* __restrict__ out)
{
    const int warp = threadIdx.x >> 5, lane = threadIdx.x & 31;
    const long row = (long)blockIdx.x * 8 + warp;
    const float4* pa = (const float4*)(a + row*D_);
    const float4* pr = (const float4*)(r + row*D_);
    const float4 rb0 = ((const float4*)rb)[lane], rb1 = ((const float4*)rb)[lane + 32];
    float4 v0 = pa[lane], v1 = pa[lane + 32];
    const float4 q0 = pr[lane], q1 = pr[lane + 32];
    v0.x += q0.x + rb0.x; v0.y += q0.y + rb0.y; v0.z += q0.z + rb0.z; v0.w += q0.w + rb0.w;
    v1.x += q1.x + rb1.x; v1.y += q1.y + rb1.y; v1.z += q1.z + rb1.z; v1.w += q1.w + rb1.w;

    float s = v0.x + v0.y + v0.z + v0.w + v1.x + v1.y + v1.z + v1.w;
#pragma unroll
    for (int o = 16; o; o >>= 1) s += __shfl_xor_sync(~0u, s, o);
    const float mu = s * (1.f / 256.f);

    float4 d0, d1;
    d0.x = v0.x - mu; d0.y = v0.y - mu; d0.z = v0.z - mu; d0.w = v0.w - mu;
    d1.x = v1.x - mu; d1.y = v1.y - mu; d1.z = v1.z - mu; d1.w = v1.w - mu;
    float var = d0.x*d0.x + d0.y*d0.y + d0.z*d0.z + d0.w*d0.w
              + d1.x*d1.x + d1.y*d1.y + d1.z*d1.z + d1.w*d1.w;
#pragma unroll
    for (int o = 16; o; o >>= 1) var += __shfl_xor_sync(~0u, var, o);
    const float rs = rsqrtf(var * (1.f / 256.f) + 1e-6f);

    const float4 g0 = ((const float4*)gam)[lane], g1 = ((const float4*)gam)[lane + 32];
    const float4 bb0 = ((const float4*)bet)[lane], bb1 = ((const float4*)bet)[lane + 32];
    float4 o0, o1;
    o0.x = d0.x*rs*g0.x + bb0.x; o0.y = d0.y*rs*g0.y + bb0.y;
    o0.z = d0.z*rs*g0.z + bb0.z; o0.w = d0.w*rs*g0.w + bb0.w;
    o1.x = d1.x*rs*g1.x + bb1.x; o1.y = d1.y*rs*g1.y + bb1.y;
    o1.z = d1.z*rs*g1.z + bb1.z; o1.w = d1.w*rs*g1.w + bb1.w;
    ((float4*)(out + row*D_))[lane]      = o0;
    ((float4*)(out + row*D_))[lane + 32] = o1;
}

// ---------------------------------------------------------------------------
// Host launch (graph-capturable)
// ---------------------------------------------------------------------------
extern "C" void kernel_launch(void* const* d_in, const int* in_sizes, int n_in,
                              void* d_out, int out_size)
{
    const float* node = (const float*)d_in[0];
    const float* edge = (const float*)d_in[1];
    const float* Wq   = (const float*)d_in[2];
    const float* Wk   = (const float*)d_in[3];
    const float* Wv   = (const float*)d_in[4];
    const float* Wp   = (const float*)d_in[5];
    const float* bp   = (const float*)d_in[6];
    const float* ln1g = (const float*)d_in[7];
    const float* ln1b = (const float*)d_in[8];
    const float* W1   = (const float*)d_in[9];
    const float* b1   = (const float*)d_in[10];
    const float* W2   = (const float*)d_in[11];
    const float* b2   = (const float*)d_in[12];
    const float* ln2g = (const float*)d_in[13];
    const float* ln2b = (const float*)d_in[14];

    float *qkv, *qe, *logits, *mo, *mha, *x, *ffh, *ff;
    float *wqkvT, *WpT, *W1T, *W2T, *vT, *part;
    cudaGetSymbolAddress((void**)&qkv,    g_qkv);
    cudaGetSymbolAddress((void**)&qe,     g_qe);
    cudaGetSymbolAddress((void**)&logits, g_logits);
    cudaGetSymbolAddress((void**)&mo,     g_mo);
    cudaGetSymbolAddress((void**)&mha,    g_mha);
    cudaGetSymbolAddress((void**)&x,      g_x);
    cudaGetSymbolAddress((void**)&ffh,    g_ffh);
    cudaGetSymbolAddress((void**)&ff,     g_ff);
    cudaGetSymbolAddress((void**)&wqkvT,  g_wqkvT);
    cudaGetSymbolAddress((void**)&WpT,    g_WpT);
    cudaGetSymbolAddress((void**)&W1T,    g_W1T);
    cudaGetSymbolAddress((void**)&W2T,    g_W2T);
    cudaGetSymbolAddress((void**)&vT,     g_vT);
    cudaGetSymbolAddress((void**)&part,   g_part);

    cudaFuncSetAttribute(edge_softmax_kernel,
                         cudaFuncAttributeMaxDynamicSharedMemorySize, EDGE_SMEM_BYTES);

    // 0) weight repacks (transposed layouts; all B operands become k-contiguous)
    repack_wqkvT<<<(D_*QKV_ + 255)/256, 256>>>(Wq, Wk, Wv, wqkvT);
    transpose_k<<<dim3(D_/32, 512/32),  dim3(32,8)>>>(Wp, WpT, 512, D_);
    transpose_k<<<dim3(FF_/32, D_/32),  dim3(32,8)>>>(W1, W1T, D_, FF_);
    transpose_k<<<dim3(D_/32, FF_/32),  dim3(32,8)>>>(W2, W2T, FF_, D_);

    // 1) fused QKV projection split-K2: qkv = node @ wqkvT^T  (768 CTAs)
    mgemm<128,64,4,2><<<dim3(QKV_/64, R_/128, 2), 256>>>(
        node, wqkvT, (const float*)0, part, D_/2,
        D_, 0, 0,
        D_, 0, 0,
        QKV_, 0, 0, 1, 2, (long)R_*QKV_);
    reduce_add<<<(R_*QKV_/4 + 255)/256, 256>>>(part, qkv, R_*QKV_/4, 2, (long)R_*QKV_/4);

    // 1b) v transpose for AV's B operand
    vt_kernel<<<dim3(512/32, N_/32, B_), dim3(32,8)>>>(qkv, vT);

    // 2) qe[r][h*64+e] = q_h[r,:] @ WkE_h^T   (z = h; 256 CTAs)
    mgemm<64,64,2,4><<<dim3(1, R_/64, H_), 256>>>(
        qkv, Wk + (long)D_*HS_, (const float*)0, qe, HS_,
        QKV_, 64, 0,
        HS_, (long)(D_+E_)*HS_, 0,
        (long)H_*E_, 64, 0, 1, 1, 0);

    // 3) QK^T logits (z = b*8+h; 2048 CTAs)
    mgemm<128,64,4,2><<<dim3(N_/64, N_/128, B_*H_), 256>>>(
        qkv, qkv + 512, (const float*)0, logits, HS_,
        QKV_, (long)N_*QKV_, 64,
        QKV_, (long)N_*QKV_, 64,
        N_, (long)H_*N_*N_, (long)N_*N_, H_, 1, 0);

    // 4) edge logits + softmax (streams 536 MB; in-place probs)
    edge_softmax_kernel<<<R_, 256, EDGE_SMEM_BYTES>>>(edge, qe, logits);

    // 5) AV split-K4: part[ks] = attn[.., chunk] @ vT[chunk]  (1024 CTAs)
    mgemm<64,64,2,4><<<dim3(1, N_/64, B_*H_*4), 256>>>(
        logits, vT, (const float*)0, part, N_/4,
        N_, (long)H_*N_*N_, (long)N_*N_,
        N_, (long)512*N_, (long)64*N_,
        (long)H_*HS_, (long)N_*H_*HS_, 64, H_, 4, (long)R_*512);
    reduce_add<<<(R_*512/4 + 255)/256, 256>>>(part, mo, R_*512/4, 4, (long)R_*512/4);

    // 6) output projection split-K2: part[ks] = mo[..,ks] @ WpT[ks]  (256 CTAs)
    mgemm<64,64,2,4><<<dim3(D_/64, R_/64, 2), 256>>>(
        mo, WpT, (const float*)0, part, (H_*HS_)/2,
        (long)H_*HS_, 0, 0,
        (long)H_*HS_, 0, 0,
        D_, 0, 0, 1, 2, (long)R_*D_);
    reduce_add<<<(R_*D_/4 + 255)/256, 256>>>(part, mha, R_*D_/4, 2, (long)R_*D_/4);

    // 7) x = LN1(node + mha + bp)
    ln_kernel<<<R_/8, 256>>>(node, mha, bp, ln1g, ln1b, x);

    // 8) FFN hidden split-K2: ffh = x @ W1  (512 CTAs; b1+relu fused into step 9)
    mgemm<128,64,4,2><<<dim3(FF_/64, R_/128, 2), 256>>>(
        x, W1T, (const float*)0, part, D_/2,
        D_, 0, 0,
        D_, 0, 0,
        FF_, 0, 0, 1, 2, (long)R_*FF_);
    reduce_add<<<(R_*FF_/4 + 255)/256, 256>>>(part, ffh, R_*FF_/4, 2, (long)R_*FF_/4);

    // 9) FFN out split-K4: part[ks] = relu(ffh+b1)[ks] @ W2T[ks]  (512 CTAs)
    mgemm<64,64,2,4><<<dim3(D_/64, R_/64, 4), 256>>>(
        ffh, W2T, b1, part, FF_/4,
        FF_, 0, 0,
        FF_, 0, 0,
        D_, 0, 0, 1, 4, (long)R_*D_);
    reduce_add<<<(R_*D_/4 + 255)/256, 256>>>(part, ff, R_*D_/4, 4, (long)R_*D_/4);

    // 10) out = LN2(x + ff + b2)
    ln_kernel<<<R_/8, 256>>>(x, ff, b2, ln2g, ln2b, (float*)d_out);
}

// round 16
// speedup vs baseline: 1.0778x; 1.0172x over previous
#include <cuda_runtime.h>
#include <cuda_bf16.h>

// Shapes (compile-time; problem is fixed-shape)
#define B_   2
#define N_   1024
#define D_   256
#define E_   64
#define H_   8
#define HS_  64
#define FF_  1024
#define R_   (B_*N_)        // 2048 token rows
#define QKV_ (3*H_*HS_)     // 1536

// ---------------------------------------------------------------------------
// Scratch (device globals; no runtime allocation allowed)
// ---------------------------------------------------------------------------
__device__ float g_qkv[R_*QKV_];                    // q | kn | v   (12 MB)
__device__ float g_qe[R_*H_*E_];                    // 4 MB
__device__ float g_logits[(long)B_*H_*N_*N_];       // 64 MB (reused as attn probs)
__device__ float g_mo[R_*H_*HS_];                   // 4 MB
__device__ float g_x[R_*D_];                        // 2 MB
__device__ float g_ffh[R_*FF_];                     // 8 MB
__device__ float g_wqkv[D_*QKV_];                   // [256][1536]
__device__ float g_part[2*R_*QKV_];                 // 25 MB split-K partials

// ---------------------------------------------------------------------------
// Repack Wq (scaled by 1/sqrt(HS)), Wk[:, :D], Wv into [256][1536] (k-major B)
// ---------------------------------------------------------------------------
__global__ void repack_wqkv(const float* __restrict__ Wq,
                            const float* __restrict__ Wk,
                            const float* __restrict__ Wv,
                            float* __restrict__ out)
{
    int idx = blockIdx.x * blockDim.x + threadIdx.x;
    if (idx >= D_ * QKV_) return;
    int i = idx / QKV_;      // input feature (0..255)
    int j = idx % QKV_;      // output column (0..1535)
    float v;
    if (j < 512) {
        int h = j >> 6, o = j & 63;
        v = Wq[(h*D_ + i)*HS_ + o] * 0.125f;               // 1/sqrt(64)
    } else if (j < 1024) {
        int jj = j - 512; int h = jj >> 6, o = jj & 63;
        v = Wk[(h*(D_+E_) + i)*HS_ + o];
    } else {
        int jj = j - 1024; int h = jj >> 6, o = jj & 63;
        v = Wv[(h*D_ + i)*HS_ + o];
    }
    out[idx] = v;
}

// ---------------------------------------------------------------------------
// Deterministic slab reduction: out[i] = sum_j part[i + j*slab4] (float4 units)
// ---------------------------------------------------------------------------
__global__ void reduce_add(const float* __restrict__ part, float* __restrict__ out,
                           int n4, int nslab, long slab4)
{
    int i = blockIdx.x * blockDim.x + threadIdx.x;
    if (i >= n4) return;
    const float4* pp = (const float4*)part;
    float4 s = pp[i];
    for (int j = 1; j < nslab; ++j) {
        float4 v = pp[i + (long)j*slab4];
        s.x += v.x; s.y += v.y; s.z += v.z; s.w += v.w;
    }
    ((float4*)out)[i] = s;
}

// ---------------------------------------------------------------------------
// tf32 helpers / PTX wrappers
// ---------------------------------------------------------------------------
__device__ __forceinline__ float f2tf32(float x)
{
    unsigned r;
    asm("cvt.rna.tf32.f32 %0, %1;" : "=r"(r) : "f"(x));
    return __uint_as_float(r);
}

__device__ __forceinline__ void mma_tf32(float* c, const unsigned* a, const unsigned* b)
{
    asm volatile("mma.sync.aligned.m16n8k8.row.col.f32.tf32.tf32.f32 "
                 "{%0,%1,%2,%3},{%4,%5,%6,%7},{%8,%9},{%0,%1,%2,%3};"
                 : "+f"(c[0]), "+f"(c[1]), "+f"(c[2]), "+f"(c[3])
                 : "r"(a[0]), "r"(a[1]), "r"(a[2]), "r"(a[3]), "r"(b[0]), "r"(b[1]));
}

// ---------------------------------------------------------------------------
// Tensor-core GEMM (tf32 mma.sync m16n8k8, single pass), fp32 I/O.
//   C[m,n] = sum_k A[m,k]*B[k,n].
//   A: K contiguous, row stride as_m.      (optional: A := relu(A + a_bias[k]))
//   B: either bs_n==1 (k-major rows: element at k*bs_k + n; staged [BK][72],
//      fragment banks (8cc+g)%32 conflict-free) or bs_k==1 (k contiguous,
//      "row" = n with stride bs_n; staged [BN][36], banks (4g+cc+..)%32 ok).
//   Batch z = (bo*inner + bi)*ksplit + ks; split-K chunk ks shifts A/bias by
//   ks*K, B by ks*K*bs_k, C by ks*c_slab (slabs reduced later).
//   All M,N,K exact multiples of tiles. BK=32. 8 warps (WM*WN==8). BN=64.
//   Single-stage static smem; next gmem tile register-prefetched.
// ---------------------------------------------------------------------------
template<int BM, int BN, int WM, int WN>
__global__ __launch_bounds__(256)
void mgemm(const float* __restrict__ A, const float* __restrict__ Bm,
           const float* __restrict__ a_bias, float* __restrict__ C,
           int K,
           long as_m, long a_bso, long a_bsi,
           long bs_k, long bs_n, long b_bso, long b_bsi,
           long cs_m, long c_bso, long c_bsi,
           int inner, int ksplit, long c_slab)
{
    const int BK  = 32;
    const int LD  = 36;                  // n-major B / A row stride (floats)
    const int LDB = BN + 8;              // k-major B row stride (72 for BN=64)
    const int NRA = BM/32;
    const int NRB = BN/32;               // = BK*BN/4/256 for BN=64
    const int WTM = BM/WM;
    const int WTN = BN/WN;
    const int FM  = WTM/16;
    const int FN  = WTN/8;

    __shared__ float4 smbuf[(BM*LD + BK*LDB)/4];   // B region fits both layouts
    float* sA = (float*)smbuf;
    float* sB = sA + BM*LD;

    const int t    = threadIdx.x;
    const int warp = t >> 5;
    const int lane = t & 31;
    const int wm   = warp / WN;
    const int wn   = warp % WN;

    const int  ks = blockIdx.z % ksplit;
    const long zz = blockIdx.z / ksplit;
    const long bo = zz / inner;
    const long bi = zz % inner;
    const long m0 = (long)blockIdx.y * BM;
    const long n0 = (long)blockIdx.x * BN;

    const float* Ab = A  + bo*a_bso + bi*a_bsi + m0*as_m + (long)ks*K;
    const float* Bb = Bm + bo*b_bso + bi*b_bsi + n0*bs_n + (long)ks*K*bs_k;
    const float* bias = a_bias ? (a_bias + (long)ks*K) : a_bias;

    const int g  = lane >> 2;          // fragment row group 0..7
    const int cc = lane & 3;           // fragment k lane 0..3
    const int kmajor = (bs_n == 1);

    float acc[FM][FN][4];
#pragma unroll
    for (int i = 0; i < FM; ++i)
#pragma unroll
        for (int j = 0; j < FN; ++j)
#pragma unroll
            for (int r = 0; r < 4; ++r) acc[i][j][r] = 0.f;

    float4 ra[NRA], rb[NRB];

    // ---- prologue: load tile 0 into registers ----
#pragma unroll
    for (int i = 0; i < NRA; ++i) {
        int f = t + i*256, row = f >> 3, c4 = (f & 7)*4;
        float4 v = *(const float4*)(Ab + (long)row*as_m + c4);
        if (bias) {
            float4 bb = *(const float4*)(bias + c4);
            v.x = fmaxf(v.x + bb.x, 0.f); v.y = fmaxf(v.y + bb.y, 0.f);
            v.z = fmaxf(v.z + bb.z, 0.f); v.w = fmaxf(v.w + bb.w, 0.f);
        }
        ra[i] = v;
    }
    if (kmajor) {
#pragma unroll
        for (int i = 0; i < NRB; ++i) {
            int f = t + i*256, rk = f / (BN/4), n4 = (f % (BN/4))*4;
            rb[i] = *(const float4*)(Bb + (long)rk*bs_k + n4);
        }
    } else {
#pragma unroll
        for (int i = 0; i < NRB; ++i) {
            int f = t + i*256, rn = f >> 3, c4 = (f & 7)*4;
            rb[i] = *(const float4*)(Bb + (long)rn*bs_n + c4);
        }
    }

    const int iters = K / BK;
#pragma unroll 1
    for (int it = 0; it < iters; ++it) {
        // ---- store register tile -> smem (tf32 round) ----
#pragma unroll
        for (int i = 0; i < NRA; ++i) {
            int f = t + i*256, row = f >> 3, c4 = (f & 7)*4;
            float4 w;
            w.x = f2tf32(ra[i].x); w.y = f2tf32(ra[i].y);
            w.z = f2tf32(ra[i].z); w.w = f2tf32(ra[i].w);
            *(float4*)(sA + row*LD + c4) = w;
        }
        if (kmajor) {
#pragma unroll
            for (int i = 0; i < NRB; ++i) {
                int f = t + i*256, rk = f / (BN/4), n4 = (f % (BN/4))*4;
                float4 w;
                w.x = f2tf32(rb[i].x); w.y = f2tf32(rb[i].y);
                w.z = f2tf32(rb[i].z); w.w = f2tf32(rb[i].w);
                *(float4*)(sB + rk*LDB + n4) = w;
            }
        } else {
#pragma unroll
            for (int i = 0; i < NRB; ++i) {
                int f = t + i*256, rn = f >> 3, c4 = (f & 7)*4;
                float4 w;
                w.x = f2tf32(rb[i].x); w.y = f2tf32(rb[i].y);
                w.z = f2tf32(rb[i].z); w.w = f2tf32(rb[i].w);
                *(float4*)(sB + rn*LD + c4) = w;
            }
        }
        __syncthreads();

        // ---- prefetch next tile into registers (overlaps mma phase) ----
        if (it + 1 < iters) {
            int k0 = (it + 1) * BK;
#pragma unroll
            for (int i = 0; i < NRA; ++i) {
                int f = t + i*256, row = f >> 3, c4 = (f & 7)*4;
                float4 v = *(const float4*)(Ab + (long)row*as_m + k0 + c4);
                if (bias) {
                    float4 bb = *(const float4*)(bias + k0 + c4);
                    v.x = fmaxf(v.x + bb.x, 0.f); v.y = fmaxf(v.y + bb.y, 0.f);
                    v.z = fmaxf(v.z + bb.z, 0.f); v.w = fmaxf(v.w + bb.w, 0.f);
                }
                ra[i] = v;
            }
            if (kmajor) {
#pragma unroll
                for (int i = 0; i < NRB; ++i) {
                    int f = t + i*256, rk = f / (BN/4), n4 = (f % (BN/4))*4;
                    rb[i] = *(const float4*)(Bb + (long)(k0 + rk)*bs_k + n4);
                }
            } else {
#pragma unroll
                for (int i = 0; i < NRB; ++i) {
                    int f = t + i*256, rn = f >> 3, c4 = (f & 7)*4;
                    rb[i] = *(const float4*)(Bb + (long)rn*bs_n + k0 + c4);
                }
            }
        }

        // ---- compute: 4 k-slices of 8 (tf32 m16n8k8) ----
#pragma unroll
        for (int ks8 = 0; ks8 < 4; ++ks8) {
            const int kb = ks8*8;
            unsigned af[FM][4], bf[FN][2];
#pragma unroll
            for (int fm = 0; fm < FM; ++fm) {
                const float* pa = sA + (wm*WTM + fm*16 + g)*LD + kb + cc;
                af[fm][0] = __float_as_uint(pa[0]);
                af[fm][1] = __float_as_uint(pa[8*LD]);
                af[fm][2] = __float_as_uint(pa[4]);
                af[fm][3] = __float_as_uint(pa[8*LD + 4]);
            }
            if (kmajor) {
#pragma unroll
                for (int fn = 0; fn < FN; ++fn) {
                    const float* pb = sB + (kb + cc)*LDB + wn*WTN + fn*8 + g;
                    bf[fn][0] = __float_as_uint(pb[0]);
                    bf[fn][1] = __float_as_uint(pb[4*LDB]);
                }
            } else {
#pragma unroll
                for (int fn = 0; fn < FN; ++fn) {
                    const float* pb = sB + (wn*WTN + fn*8 + g)*LD + kb + cc;
                    bf[fn][0] = __float_as_uint(pb[0]);
                    bf[fn][1] = __float_as_uint(pb[4]);
                }
            }
#pragma unroll
            for (int fm = 0; fm < FM; ++fm)
#pragma unroll
                for (int fn = 0; fn < FN; ++fn)
                    mma_tf32(acc[fm][fn], af[fm], bf[fn]);
        }
        __syncthreads();
    }

    // ---- epilogue ----
    const int tig = lane & 3;
    float* Cb = C + bo*c_bso + bi*c_bsi + (long)ks*c_slab;
#pragma unroll
    for (int fm = 0; fm < FM; ++fm) {
#pragma unroll
        for (int fn = 0; fn < FN; ++fn) {
            float* p = Cb + (m0 + wm*WTM + fm*16 + g)*cs_m
                          + n0 + wn*WTN + fn*8 + 2*tig;
            float2 v0; v0.x = acc[fm][fn][0]; v0.y = acc[fm][fn][1];
            float2 v1; v1.x = acc[fm][fn][2]; v1.y = acc[fm][fn][3];
            *(float2*)p            = v0;
            *(float2*)(p + 8*cs_m) = v1;
        }
    }
}

// ---------------------------------------------------------------------------
// Edge-conditioned logits + softmax, fused. One CTA per (b, n). 256 threads.
// Register-prefetch double buffering (tile mt+1 loads overlap compute of mt).
// ---------------------------------------------------------------------------
#define EDGE_SMEM_BYTES ((8192 + 256*17*4 + 128*4) * 4)   // 104448

__global__ __launch_bounds__(256)
void edge_softmax_kernel(const float* __restrict__ edge,
                         const float* __restrict__ qe,
                         float* __restrict__ logits)
{
    extern __shared__ float smem[];
    float*  s_logits = smem;                       // 8192 floats
    float4* s_edge4  = (float4*)(smem + 8192);     // 256*17 float4
    float4* s_qe4    = s_edge4 + 256*17;           // 128 float4

    const int t  = threadIdx.x;
    const int bn = blockIdx.x;
    const int b  = bn >> 10;
    const int n  = bn & 1023;

    if (t < 128) s_qe4[t] = ((const float4*)(qe + (long)bn*512))[t];

    const float* lg = logits + ((long)(b*H_)*N_ + n) * N_;
#pragma unroll
    for (int h = 0; h < H_; ++h) {
        const float4* src = (const float4*)(lg + (long)h*N_*N_);
        ((float4*)(s_logits + h*N_))[t] = src[t];
    }

    const float4* eg = (const float4*)(edge + ((long)bn << 16));
    const int tx = t & 63;            // m lane
    const int hg = t >> 6;            // head group 0..3 -> heads {2hg, 2hg+1}

    float4 rg[16];
#pragma unroll
    for (int i = 0; i < 16; ++i) rg[i] = eg[t + i*256];

    __syncthreads();   // covers s_logits/qe init

    for (int mt = 0; mt < 4; ++mt) {
#pragma unroll
        for (int i = 0; i < 16; ++i) {
            int f = t + i*256;
            s_edge4[(f >> 4)*17 + (f & 15)] = rg[i];
        }
        __syncthreads();

        if (mt + 1 < 4) {
#pragma unroll
            for (int i = 0; i < 16; ++i)
                rg[i] = eg[(mt + 1)*4096 + t + i*256];
        }

        float acc[4][2];
#pragma unroll
        for (int i = 0; i < 4; ++i) {
            acc[i][0] = 0.f; acc[i][1] = 0.f;
        }

#pragma unroll
        for (int e4 = 0; e4 < 16; ++e4) {
            float4 ev[4], qv[2];
#pragma unroll
            for (int i = 0; i < 4; ++i) ev[i] = s_edge4[(tx + i*64)*17 + e4];
            qv[0] = s_qe4[(hg*2 + 0)*16 + e4];
            qv[1] = s_qe4[(hg*2 + 1)*16 + e4];
#pragma unroll
            for (int i = 0; i < 4; ++i) {
                acc[i][0] += ev[i].x*qv[0].x + ev[i].y*qv[0].y
                           + ev[i].z*qv[0].z + ev[i].w*qv[0].w;
                acc[i][1] += ev[i].x*qv[1].x + ev[i].y*qv[1].y
                           + ev[i].z*qv[1].z + ev[i].w*qv[1].w;
            }
        }
#pragma unroll
        for (int j = 0; j < 2; ++j)
#pragma unroll
            for (int i = 0; i < 4; ++i)
                s_logits[(hg*2 + j)*N_ + mt*256 + i*64 + tx] += acc[i][j];
        __syncthreads();
    }

    const int warp = t >> 5, lane = t & 31;
    for (int h = warp; h < H_; h += 8) {
        const float* row = s_logits + h*N_;
        float mx = -1e30f;
#pragma unroll
        for (int i = 0; i < 32; ++i) mx = fmaxf(mx, row[lane + i*32]);
#pragma unroll
        for (int o = 16; o; o >>= 1) mx = fmaxf(mx, __shfl_xor_sync(~0u, mx, o));
        float vals[32];
        float sum = 0.f;
#pragma unroll
        for (int i = 0; i < 32; ++i) {
            vals[i] = __expf(row[lane + i*32] - mx);
            sum += vals[i];
        }
#pragma unroll
        for (int o = 16; o; o >>= 1) sum += __shfl_xor_sync(~0u, sum, o);
        const float inv = 1.f / sum;
        float* out = logits + ((long)(b*H_ + h)*N_ + n) * N_;
#pragma unroll
        for (int i = 0; i < 32; ++i) out[lane + i*32] = vals[i] * inv;
    }
}

// ---------------------------------------------------------------------------
// LayerNorm over last dim (256), fused residual + split-K slab sum + bias.
// out = LN(a + sum_j part[.. + j*slab] + rb) * g + beta.  Warp per row.
// ---------------------------------------------------------------------------
__global__ __launch_bounds__(256)
void ln_kernel(const float* __restrict__ a, const float* __restrict__ part,
               int nslab, long slab4,
               const float* __restrict__ rb,
               const float* __restrict__ gam, const float* __restrict__ bet,
               float* __restrict__ out)
{
    const int warp = threadIdx.x >> 5, lane = threadIdx.x & 31;
    const long row = (long)blockIdx.x * 8 + warp;
    const long i0 = row*64 + lane;          // float4 index
    const float4* pa = (const float4*)a;
    const float4* pp = (const float4*)part;
    const float4 rb0 = ((const float4*)rb)[lane], rb1 = ((const float4*)rb)[lane + 32];

    float4 v0 = pa[i0], v1 = pa[i0 + 32];
    for (int j = 0; j < nslab; ++j) {
        float4 q0 = pp[i0 + (long)j*slab4];
        float4 q1 = pp[i0 + 32 + (long)j*slab4];
        v0.x += q0.x; v0.y += q0.y; v0.z += q0.z; v0.w += q0.w;
        v1.x += q1.x; v1.y += q1.y; v1.z += q1.z; v1.w += q1.w;
    }
    v0.x += rb0.x; v0.y += rb0.y; v0.z += rb0.z; v0.w += rb0.w;
    v1.x += rb1.x; v1.y += rb1.y; v1.z += rb1.z; v1.w += rb1.w;

    float s = v0.x + v0.y + v0.z + v0.w + v1.x + v1.y + v1.z + v1.w;
#pragma unroll
    for (int o = 16; o; o >>= 1) s += __shfl_xor_sync(~0u, s, o);
    const float mu = s * (1.f / 256.f);

    float4 d0, d1;
    d0.x = v0.x - mu; d0.y = v0.y - mu; d0.z = v0.z - mu; d0.w = v0.w - mu;
    d1.x = v1.x - mu; d1.y = v1.y - mu; d1.z = v1.z - mu; d1.w = v1.w - mu;
    float var = d0.x*d0.x + d0.y*d0.y + d0.z*d0.z + d0.w*d0.w
              + d1.x*d1.x + d1.y*d1.y + d1.z*d1.z + d1.w*d1.w;
#pragma unroll
    for (int o = 16; o; o >>= 1) var += __shfl_xor_sync(~0u, var, o);
    const float rs = rsqrtf(var * (1.f / 256.f) + 1e-6f);

    const float4 g0 = ((const float4*)gam)[lane], g1 = ((const float4*)gam)[lane + 32];
    const float4 bb0 = ((const float4*)bet)[lane], bb1 = ((const float4*)bet)[lane + 32];
    float4 o0, o1;
    o0.x = d0.x*rs*g0.x + bb0.x; o0.y = d0.y*rs*g0.y + bb0.y;
    o0.z = d0.z*rs*g0.z + bb0.z; o0.w = d0.w*rs*g0.w + bb0.w;
    o1.x = d1.x*rs*g1.x + bb1.x; o1.y = d1.y*rs*g1.y + bb1.y;
    o1.z = d1.z*rs*g1.z + bb1.z; o1.w = d1.w*rs*g1.w + bb1.w;
    ((float4*)out)[i0]      = o0;
    ((float4*)out)[i0 + 32] = o1;
}

// ---------------------------------------------------------------------------
// Host launch (graph-capturable)
// ---------------------------------------------------------------------------
extern "C" void kernel_launch(void* const* d_in, const int* in_sizes, int n_in,
                              void* d_out, int out_size)
{
    const float* node = (const float*)d_in[0];
    const float* edge = (const float*)d_in[1];
    const float* Wq   = (const float*)d_in[2];
    const float* Wk   = (const float*)d_in[3];
    const float* Wv   = (const float*)d_in[4];
    const float* Wp   = (const float*)d_in[5];
    const float* bp   = (const float*)d_in[6];
    const float* ln1g = (const float*)d_in[7];
    const float* ln1b = (const float*)d_in[8];
    const float* W1   = (const float*)d_in[9];
    const float* b1   = (const float*)d_in[10];
    const float* W2   = (const float*)d_in[11];
    const float* b2   = (const float*)d_in[12];
    const float* ln2g = (const float*)d_in[13];
    const float* ln2b = (const float*)d_in[14];

    float *qkv, *qe, *logits, *mo, *x, *ffh, *wqkv, *part;
    cudaGetSymbolAddress((void**)&qkv,    g_qkv);
    cudaGetSymbolAddress((void**)&qe,     g_qe);
    cudaGetSymbolAddress((void**)&logits, g_logits);
    cudaGetSymbolAddress((void**)&mo,     g_mo);
    cudaGetSymbolAddress((void**)&x,      g_x);
    cudaGetSymbolAddress((void**)&ffh,    g_ffh);
    cudaGetSymbolAddress((void**)&wqkv,   g_wqkv);
    cudaGetSymbolAddress((void**)&part,   g_part);

    cudaFuncSetAttribute(edge_softmax_kernel,
                         cudaFuncAttributeMaxDynamicSharedMemorySize, EDGE_SMEM_BYTES);

    // 0) weight repack (k-major [256][1536])
    repack_wqkv<<<(D_*QKV_ + 255)/256, 256>>>(Wq, Wk, Wv, wqkv);

    // 1) fused QKV projection split-K2: qkv = node @ wqkv  (768 CTAs)
    mgemm<128,64,4,2><<<dim3(QKV_/64, R_/128, 2), 256>>>(
        node, wqkv, (const float*)0, part, D_/2,
        D_, 0, 0,
        QKV_, 1, 0, 0,
        QKV_, 0, 0, 1, 2, (long)R_*QKV_);
    reduce_add<<<(R_*QKV_/4 + 255)/256, 256>>>(part, qkv, R_*QKV_/4, 2, (long)R_*QKV_/4);

    // 2) qe[r][h*64+e] = q_h[r,:] @ WkE_h^T   (z = h; 256 CTAs; n-major B)
    mgemm<64,64,2,4><<<dim3(1, R_/64, H_), 256>>>(
        qkv, Wk + (long)D_*HS_, (const float*)0, qe, HS_,
        QKV_, 64, 0,
        1, HS_, (long)(D_+E_)*HS_, 0,
        (long)H_*E_, 64, 0, 1, 1, 0);

    // 3) QK^T logits (z = b*8+h; 2048 CTAs; n-major B = kn)
    mgemm<128,64,4,2><<<dim3(N_/64, N_/128, B_*H_), 256>>>(
        qkv, qkv + 512, (const float*)0, logits, HS_,
        QKV_, (long)N_*QKV_, 64,
        1, QKV_, (long)N_*QKV_, 64,
        N_, (long)H_*N_*N_, (long)N_*N_, H_, 1, 0);

    // 4) edge logits + softmax (streams 536 MB; in-place probs)
    edge_softmax_kernel<<<R_, 256, EDGE_SMEM_BYTES>>>(edge, qe, logits);

    // 5) AV split-K4: part[ks] = attn[.., chunk] @ v[chunk]  (1024 CTAs; k-major B)
    mgemm<64,64,2,4><<<dim3(1, N_/64, B_*H_*4), 256>>>(
        logits, qkv + 1024, (const float*)0, part, N_/4,
        N_, (long)H_*N_*N_, (long)N_*N_,
        QKV_, 1, (long)N_*QKV_, 64,
        (long)H_*HS_, (long)N_*H_*HS_, 64, H_, 4, (long)R_*512);
    reduce_add<<<(R_*512/4 + 255)/256, 256>>>(part, mo, R_*512/4, 4, (long)R_*512/4);

    // 6) output projection split-K2: part[ks] = mo[..,ks] @ Wp[ks]  (256 CTAs)
    mgemm<64,64,2,4><<<dim3(D_/64, R_/64, 2), 256>>>(
        mo, Wp, (const float*)0, part, (H_*HS_)/2,
        (long)H_*HS_, 0, 0,
        D_, 1, 0, 0,
        D_, 0, 0, 1, 2, (long)R_*D_);

    // 7) x = LN1(node + part0 + part1 + bp)   (reduce fused into LN)
    ln_kernel<<<R_/8, 256>>>(node, part, 2, (long)R_*D_/4, bp, ln1g, ln1b, x);

    // 8) FFN hidden split-K2: ffh = x @ W1  (512 CTAs; b1+relu fused into step 9)
    mgemm<128,64,4,2><<<dim3(FF_/64, R_/128, 2), 256>>>(
        x, W1, (const float*)0, part, D_/2,
        D_, 0, 0,
        FF_, 1, 0, 0,
        FF_, 0, 0, 1, 2, (long)R_*FF_);
    reduce_add<<<(R_*FF_/4 + 255)/256, 256>>>(part, ffh, R_*FF_/4, 2, (long)R_*FF_/4);

    // 9) FFN out split-K4: part[ks] = relu(ffh+b1)[ks] @ W2[ks]  (512 CTAs)
    mgemm<64,64,2,4><<<dim3(D_/64, R_/64, 4), 256>>>(
        ffh, W2, b1, part, FF_/4,
        FF_, 0, 0,
        D_, 1, 0, 0,
        D_, 0, 0, 1, 4, (long)R_*D_);

    // 10) out = LN2(x + part0..3 + b2)   (reduce fused into LN)
    ln_kernel<<<R_/8, 256>>>(x, part, 4, (long)R_*D_/4, b2, ln2g, ln2b, (float*)d_out);
}

// round 17
// speedup vs baseline: 1.1919x; 1.1060x over previous
#include <cuda_runtime.h>
#include <cuda_bf16.h>

// Shapes (compile-time; problem is fixed-shape)
#define B_   2
#define N_   1024
#define D_   256
#define E_   64
#define H_   8
#define HS_  64
#define FF_  1024
#define R_   (B_*N_)        // 2048 token rows
#define QKV_ (3*H_*HS_)     // 1536

// ---------------------------------------------------------------------------
// Scratch (device globals; no runtime allocation allowed)
// ---------------------------------------------------------------------------
__device__ float g_qkv[R_*QKV_];                    // q | kn | v   (12 MB)
__device__ float g_qe[R_*H_*E_];                    // 4 MB
__device__ float g_logits[(long)B_*H_*N_*N_];       // 64 MB (reused as attn probs)
__device__ float g_mo[R_*H_*HS_];                   // 4 MB
__device__ float g_x[R_*D_];                        // 2 MB
__device__ float g_ffh[R_*FF_];                     // 8 MB
__device__ float g_wqkv[D_*QKV_];                   // [256][1536]
__device__ float g_part[2*R_*QKV_];                 // 25 MB split-K partials

// ---------------------------------------------------------------------------
// Repack Wq (scaled by 1/sqrt(HS)), Wk[:, :D], Wv into [256][1536] (k-major B)
// ---------------------------------------------------------------------------
__global__ void repack_wqkv(const float* __restrict__ Wq,
                            const float* __restrict__ Wk,
                            const float* __restrict__ Wv,
                            float* __restrict__ out)
{
    int idx = blockIdx.x * blockDim.x + threadIdx.x;
    if (idx >= D_ * QKV_) return;
    int i = idx / QKV_;      // input feature (0..255)
    int j = idx % QKV_;      // output column (0..1535)
    float v;
    if (j < 512) {
        int h = j >> 6, o = j & 63;
        v = Wq[(h*D_ + i)*HS_ + o] * 0.125f;               // 1/sqrt(64)
    } else if (j < 1024) {
        int jj = j - 512; int h = jj >> 6, o = jj & 63;
        v = Wk[(h*(D_+E_) + i)*HS_ + o];
    } else {
        int jj = j - 1024; int h = jj >> 6, o = jj & 63;
        v = Wv[(h*D_ + i)*HS_ + o];
    }
    out[idx] = v;
}

// ---------------------------------------------------------------------------
// Deterministic slab reduction: out[i] = sum_j part[i + j*slab4] (float4 units)
// ---------------------------------------------------------------------------
__global__ void reduce_add(const float* __restrict__ part, float* __restrict__ out,
                           int n4, int nslab, long slab4)
{
    int i = blockIdx.x * blockDim.x + threadIdx.x;
    if (i >= n4) return;
    const float4* pp = (const float4*)part;
    float4 s = pp[i];
    for (int j = 1; j < nslab; ++j) {
        float4 v = pp[i + (long)j*slab4];
        s.x += v.x; s.y += v.y; s.z += v.z; s.w += v.w;
    }
    ((float4*)out)[i] = s;
}

// ---------------------------------------------------------------------------
// tf32 helpers / PTX wrappers
// ---------------------------------------------------------------------------
__device__ __forceinline__ float f2tf32(float x)
{
    unsigned r;
    asm("cvt.rna.tf32.f32 %0, %1;" : "=r"(r) : "f"(x));
    return __uint_as_float(r);
}

__device__ __forceinline__ void mma_tf32(float* c, const unsigned* a, const unsigned* b)
{
    asm volatile("mma.sync.aligned.m16n8k8.row.col.f32.tf32.tf32.f32 "
                 "{%0,%1,%2,%3},{%4,%5,%6,%7},{%8,%9},{%0,%1,%2,%3};"
                 : "+f"(c[0]), "+f"(c[1]), "+f"(c[2]), "+f"(c[3])
                 : "r"(a[0]), "r"(a[1]), "r"(a[2]), "r"(a[3]), "r"(b[0]), "r"(b[1]));
}

// ---------------------------------------------------------------------------
// Tensor-core GEMM (tf32 mma.sync m16n8k8, single pass), fp32 I/O.
//   C[m,n] = sum_k A[m,k]*B[k,n].
//   A: K contiguous, row stride as_m.      (optional: A := relu(A + a_bias[k]))
//   B: either bs_n==1 (k-major rows: element at k*bs_k + n; staged [BK][72],
//      fragment banks (8cc+g)%32 conflict-free) or bs_k==1 (k contiguous,
//      "row" = n with stride bs_n; staged [BN][36], banks (4g+cc+..)%32 ok).
//   Batch z = (bo*inner + bi)*ksplit + ks; split-K chunk ks shifts A/bias by
//   ks*K, B by ks*K*bs_k, C by ks*c_slab (slabs reduced later).
//   All M,N,K exact multiples of tiles. BK=32. 8 warps (WM*WN==8). BN=64.
//   Single-stage static smem; next gmem tile register-prefetched.
// ---------------------------------------------------------------------------
template<int BM, int BN, int WM, int WN>
__global__ __launch_bounds__(256)
void mgemm(const float* __restrict__ A, const float* __restrict__ Bm,
           const float* __restrict__ a_bias, float* __restrict__ C,
           int K,
           long as_m, long a_bso, long a_bsi,
           long bs_k, long bs_n, long b_bso, long b_bsi,
           long cs_m, long c_bso, long c_bsi,
           int inner, int ksplit, long c_slab)
{
    const int BK  = 32;
    const int LD  = 36;                  // n-major B / A row stride (floats)
    const int LDB = BN + 8;              // k-major B row stride (72 for BN=64)
    const int NRA = BM/32;
    const int NRB = BN/32;               // = BK*BN/4/256 for BN=64
    const int WTM = BM/WM;
    const int WTN = BN/WN;
    const int FM  = WTM/16;
    const int FN  = WTN/8;

    __shared__ float4 smbuf[(BM*LD + BK*LDB)/4];   // B region fits both layouts
    float* sA = (float*)smbuf;
    float* sB = sA + BM*LD;

    const int t    = threadIdx.x;
    const int warp = t >> 5;
    const int lane = t & 31;
    const int wm   = warp / WN;
    const int wn   = warp % WN;

    const int  ks = blockIdx.z % ksplit;
    const long zz = blockIdx.z / ksplit;
    const long bo = zz / inner;
    const long bi = zz % inner;
    const long m0 = (long)blockIdx.y * BM;
    const long n0 = (long)blockIdx.x * BN;

    const float* Ab = A  + bo*a_bso + bi*a_bsi + m0*as_m + (long)ks*K;
    const float* Bb = Bm + bo*b_bso + bi*b_bsi + n0*bs_n + (long)ks*K*bs_k;
    const float* bias = a_bias ? (a_bias + (long)ks*K) : a_bias;

    const int g  = lane >> 2;          // fragment row group 0..7
    const int cc = lane & 3;           // fragment k lane 0..3
    const int kmajor = (bs_n == 1);

    float acc[FM][FN][4];
#pragma unroll
    for (int i = 0; i < FM; ++i)
#pragma unroll
        for (int j = 0; j < FN; ++j)
#pragma unroll
            for (int r = 0; r < 4; ++r) acc[i][j][r] = 0.f;

    float4 ra[NRA], rb[NRB];

    // ---- prologue: load tile 0 into registers ----
#pragma unroll
    for (int i = 0; i < NRA; ++i) {
        int f = t + i*256, row = f >> 3, c4 = (f & 7)*4;
        float4 v = *(const float4*)(Ab + (long)row*as_m + c4);
        if (bias) {
            float4 bb = *(const float4*)(bias + c4);
            v.x = fmaxf(v.x + bb.x, 0.f); v.y = fmaxf(v.y + bb.y, 0.f);
            v.z = fmaxf(v.z + bb.z, 0.f); v.w = fmaxf(v.w + bb.w, 0.f);
        }
        ra[i] = v;
    }
    if (kmajor) {
#pragma unroll
        for (int i = 0; i < NRB; ++i) {
            int f = t + i*256, rk = f / (BN/4), n4 = (f % (BN/4))*4;
            rb[i] = *(const float4*)(Bb + (long)rk*bs_k + n4);
        }
    } else {
#pragma unroll
        for (int i = 0; i < NRB; ++i) {
            int f = t + i*256, rn = f >> 3, c4 = (f & 7)*4;
            rb[i] = *(const float4*)(Bb + (long)rn*bs_n + c4);
        }
    }

    const int iters = K / BK;
#pragma unroll 1
    for (int it = 0; it < iters; ++it) {
        // ---- store register tile -> smem (tf32 round) ----
#pragma unroll
        for (int i = 0; i < NRA; ++i) {
            int f = t + i*256, row = f >> 3, c4 = (f & 7)*4;
            float4 w;
            w.x = f2tf32(ra[i].x); w.y = f2tf32(ra[i].y);
            w.z = f2tf32(ra[i].z); w.w = f2tf32(ra[i].w);
            *(float4*)(sA + row*LD + c4) = w;
        }
        if (kmajor) {
#pragma unroll
            for (int i = 0; i < NRB; ++i) {
                int f = t + i*256, rk = f / (BN/4), n4 = (f % (BN/4))*4;
                float4 w;
                w.x = f2tf32(rb[i].x); w.y = f2tf32(rb[i].y);
                w.z = f2tf32(rb[i].z); w.w = f2tf32(rb[i].w);
                *(float4*)(sB + rk*LDB + n4) = w;
            }
        } else {
#pragma unroll
            for (int i = 0; i < NRB; ++i) {
                int f = t + i*256, rn = f >> 3, c4 = (f & 7)*4;
                float4 w;
                w.x = f2tf32(rb[i].x); w.y = f2tf32(rb[i].y);
                w.z = f2tf32(rb[i].z); w.w = f2tf32(rb[i].w);
                *(float4*)(sB + rn*LD + c4) = w;
            }
        }
        __syncthreads();

        // ---- prefetch next tile into registers (overlaps mma phase) ----
        if (it + 1 < iters) {
            int k0 = (it + 1) * BK;
#pragma unroll
            for (int i = 0; i < NRA; ++i) {
                int f = t + i*256, row = f >> 3, c4 = (f & 7)*4;
                float4 v = *(const float4*)(Ab + (long)row*as_m + k0 + c4);
                if (bias) {
                    float4 bb = *(const float4*)(bias + k0 + c4);
                    v.x = fmaxf(v.x + bb.x, 0.f); v.y = fmaxf(v.y + bb.y, 0.f);
                    v.z = fmaxf(v.z + bb.z, 0.f); v.w = fmaxf(v.w + bb.w, 0.f);
                }
                ra[i] = v;
            }
            if (kmajor) {
#pragma unroll
                for (int i = 0; i < NRB; ++i) {
                    int f = t + i*256, rk = f / (BN/4), n4 = (f % (BN/4))*4;
                    rb[i] = *(const float4*)(Bb + (long)(k0 + rk)*bs_k + n4);
                }
            } else {
#pragma unroll
                for (int i = 0; i < NRB; ++i) {
                    int f = t + i*256, rn = f >> 3, c4 = (f & 7)*4;
                    rb[i] = *(const float4*)(Bb + (long)rn*bs_n + k0 + c4);
                }
            }
        }

        // ---- compute: 4 k-slices of 8 (tf32 m16n8k8) ----
#pragma unroll
        for (int ks8 = 0; ks8 < 4; ++ks8) {
            const int kb = ks8*8;
            unsigned af[FM][4], bf[FN][2];
#pragma unroll
            for (int fm = 0; fm < FM; ++fm) {
                const float* pa = sA + (wm*WTM + fm*16 + g)*LD + kb + cc;
                af[fm][0] = __float_as_uint(pa[0]);
                af[fm][1] = __float_as_uint(pa[8*LD]);
                af[fm][2] = __float_as_uint(pa[4]);
                af[fm][3] = __float_as_uint(pa[8*LD + 4]);
            }
            if (kmajor) {
#pragma unroll
                for (int fn = 0; fn < FN; ++fn) {
                    const float* pb = sB + (kb + cc)*LDB + wn*WTN + fn*8 + g;
                    bf[fn][0] = __float_as_uint(pb[0]);
                    bf[fn][1] = __float_as_uint(pb[4*LDB]);
                }
            } else {
#pragma unroll
                for (int fn = 0; fn < FN; ++fn) {
                    const float* pb = sB + (wn*WTN + fn*8 + g)*LD + kb + cc;
                    bf[fn][0] = __float_as_uint(pb[0]);
                    bf[fn][1] = __float_as_uint(pb[4]);
                }
            }
#pragma unroll
            for (int fm = 0; fm < FM; ++fm)
#pragma unroll
                for (int fn = 0; fn < FN; ++fn)
                    mma_tf32(acc[fm][fn], af[fm], bf[fn]);
        }
        __syncthreads();
    }

    // ---- epilogue ----
    const int tig = lane & 3;
    float* Cb = C + bo*c_bso + bi*c_bsi + (long)ks*c_slab;
#pragma unroll
    for (int fm = 0; fm < FM; ++fm) {
#pragma unroll
        for (int fn = 0; fn < FN; ++fn) {
            float* p = Cb + (m0 + wm*WTM + fm*16 + g)*cs_m
                          + n0 + wn*WTN + fn*8 + 2*tig;
            float2 v0; v0.x = acc[fm][fn][0]; v0.y = acc[fm][fn][1];
            float2 v1; v1.x = acc[fm][fn][2]; v1.y = acc[fm][fn][3];
            *(float2*)p            = v0;
            *(float2*)(p + 8*cs_m) = v1;
        }
    }
}

// ---------------------------------------------------------------------------
// Edge-conditioned logits + softmax, fused. One CTA per (b, n). 256 threads.
// 128-row edge tiles (8 iterations): smem 69632 B -> 3 CTAs/SM (24 warps),
// higher DRAM-stream parallelism. Register-prefetch double buffering kept.
// ---------------------------------------------------------------------------
#define EDGE_SMEM_BYTES ((8192 + 128*17*4 + 128*4) * 4)   // 69632

__global__ __launch_bounds__(256)
void edge_softmax_kernel(const float* __restrict__ edge,
                         const float* __restrict__ qe,
                         float* __restrict__ logits)
{
    extern __shared__ float smem[];
    float*  s_logits = smem;                       // 8192 floats
    float4* s_edge4  = (float4*)(smem + 8192);     // 128*17 float4
    float4* s_qe4    = s_edge4 + 128*17;           // 128 float4

    const int t  = threadIdx.x;
    const int bn = blockIdx.x;
    const int b  = bn >> 10;
    const int n  = bn & 1023;

    if (t < 128) s_qe4[t] = ((const float4*)(qe + (long)bn*512))[t];

    // init s_logits with QK logits (256 float4 per head, 1 per thread)
    const float* lg = logits + ((long)(b*H_)*N_ + n) * N_;
#pragma unroll
    for (int h = 0; h < H_; ++h) {
        const float4* src = (const float4*)(lg + (long)h*N_*N_);
        ((float4*)(s_logits + h*N_))[t] = src[t];
    }

    const float4* eg = (const float4*)(edge + ((long)bn << 16));
    const int tx = t & 63;            // m lane
    const int hg = t >> 6;            // head group 0..3 -> heads {2hg, 2hg+1}

    // prologue: tile 0 (128 rows = 2048 float4, 8 per thread) -> registers
    float4 rg[8];
#pragma unroll
    for (int i = 0; i < 8; ++i) rg[i] = eg[t + i*256];

    __syncthreads();   // covers s_logits/qe init

    for (int mt = 0; mt < 8; ++mt) {
        // ---- store register tile -> smem (swizzled rows of 17 f4) ----
#pragma unroll
        for (int i = 0; i < 8; ++i) {
            int f = t + i*256;
            s_edge4[(f >> 4)*17 + (f & 15)] = rg[i];
        }
        __syncthreads();

        // ---- prefetch next tile into registers (overlaps compute) ----
        if (mt + 1 < 8) {
#pragma unroll
            for (int i = 0; i < 8; ++i)
                rg[i] = eg[(mt + 1)*2048 + t + i*256];
        }

        float acc[2][2];
        acc[0][0] = 0.f; acc[0][1] = 0.f;
        acc[1][0] = 0.f; acc[1][1] = 0.f;

#pragma unroll
        for (int e4 = 0; e4 < 16; ++e4) {
            float4 ev[2], qv[2];
            ev[0] = s_edge4[(tx      )*17 + e4];
            ev[1] = s_edge4[(tx +  64)*17 + e4];
            qv[0] = s_qe4[(hg*2 + 0)*16 + e4];
            qv[1] = s_qe4[(hg*2 + 1)*16 + e4];
#pragma unroll
            for (int i = 0; i < 2; ++i) {
                acc[i][0] += ev[i].x*qv[0].x + ev[i].y*qv[0].y
                           + ev[i].z*qv[0].z + ev[i].w*qv[0].w;
                acc[i][1] += ev[i].x*qv[1].x + ev[i].y*qv[1].y
                           + ev[i].z*qv[1].z + ev[i].w*qv[1].w;
            }
        }
#pragma unroll
        for (int j = 0; j < 2; ++j)
#pragma unroll
            for (int i = 0; i < 2; ++i)
                s_logits[(hg*2 + j)*N_ + mt*128 + i*64 + tx] += acc[i][j];
        __syncthreads();
    }

    // softmax: one warp per head (8 warps, 8 heads)
    const int warp = t >> 5, lane = t & 31;
    for (int h = warp; h < H_; h += 8) {
        const float* row = s_logits + h*N_;
        float mx = -1e30f;
#pragma unroll
        for (int i = 0; i < 32; ++i) mx = fmaxf(mx, row[lane + i*32]);
#pragma unroll
        for (int o = 16; o; o >>= 1) mx = fmaxf(mx, __shfl_xor_sync(~0u, mx, o));
        float vals[32];
        float sum = 0.f;
#pragma unroll
        for (int i = 0; i < 32; ++i) {
            vals[i] = __expf(row[lane + i*32] - mx);
            sum += vals[i];
        }
#pragma unroll
        for (int o = 16; o; o >>= 1) sum += __shfl_xor_sync(~0u, sum, o);
        const float inv = 1.f / sum;
        float* out = logits + ((long)(b*H_ + h)*N_ + n) * N_;
#pragma unroll
        for (int i = 0; i < 32; ++i) out[lane + i*32] = vals[i] * inv;
    }
}

// ---------------------------------------------------------------------------
// LayerNorm over last dim (256), fused residual + split-K slab sum + bias.
// out = LN(a + sum_j part[.. + j*slab] + rb) * g + beta.  Warp per row.
// ---------------------------------------------------------------------------
__global__ __launch_bounds__(256)
void ln_kernel(const float* __restrict__ a, const float* __restrict__ part,
               int nslab, long slab4,
               const float* __restrict__ rb,
               const float* __restrict__ gam, const float* __restrict__ bet,
               float* __restrict__ out)
{
    const int warp = threadIdx.x >> 5, lane = threadIdx.x & 31;
    const long row = (long)blockIdx.x * 8 + warp;
    const long i0 = row*64 + lane;          // float4 index
    const float4* pa = (const float4*)a;
    const float4* pp = (const float4*)part;
    const float4 rb0 = ((const float4*)rb)[lane], rb1 = ((const float4*)rb)[lane + 32];

    float4 v0 = pa[i0], v1 = pa[i0 + 32];
    for (int j = 0; j < nslab; ++j) {
        float4 q0 = pp[i0 + (long)j*slab4];
        float4 q1 = pp[i0 + 32 + (long)j*slab4];
        v0.x += q0.x; v0.y += q0.y; v0.z += q0.z; v0.w += q0.w;
        v1.x += q1.x; v1.y += q1.y; v1.z += q1.z; v1.w += q1.w;
    }
    v0.x += rb0.x; v0.y += rb0.y; v0.z += rb0.z; v0.w += rb0.w;
    v1.x += rb1.x; v1.y += rb1.y; v1.z += rb1.z; v1.w += rb1.w;

    float s = v0.x + v0.y + v0.z + v0.w + v1.x + v1.y + v1.z + v1.w;
#pragma unroll
    for (int o = 16; o; o >>= 1) s += __shfl_xor_sync(~0u, s, o);
    const float mu = s * (1.f / 256.f);

    float4 d0, d1;
    d0.x = v0.x - mu; d0.y = v0.y - mu; d0.z = v0.z - mu; d0.w = v0.w - mu;
    d1.x = v1.x - mu; d1.y = v1.y - mu; d1.z = v1.z - mu; d1.w = v1.w - mu;
    float var = d0.x*d0.x + d0.y*d0.y + d0.z*d0.z + d0.w*d0.w
              + d1.x*d1.x + d1.y*d1.y + d1.z*d1.z + d1.w*d1.w;
#pragma unroll
    for (int o = 16; o; o >>= 1) var += __shfl_xor_sync(~0u, var, o);
    const float rs = rsqrtf(var * (1.f / 256.f) + 1e-6f);

    const float4 g0 = ((const float4*)gam)[lane], g1 = ((const float4*)gam)[lane + 32];
    const float4 bb0 = ((const float4*)bet)[lane], bb1 = ((const float4*)bet)[lane + 32];
    float4 o0, o1;
    o0.x = d0.x*rs*g0.x + bb0.x; o0.y = d0.y*rs*g0.y + bb0.y;
    o0.z = d0.z*rs*g0.z + bb0.z; o0.w = d0.w*rs*g0.w + bb0.w;
    o1.x = d1.x*rs*g1.x + bb1.x; o1.y = d1.y*rs*g1.y + bb1.y;
    o1.z = d1.z*rs*g1.z + bb1.z; o1.w = d1.w*rs*g1.w + bb1.w;
    ((float4*)out)[i0]      = o0;
    ((float4*)out)[i0 + 32] = o1;
}

// ---------------------------------------------------------------------------
// Host launch (graph-capturable)
// ---------------------------------------------------------------------------
extern "C" void kernel_launch(void* const* d_in, const int* in_sizes, int n_in,
                              void* d_out, int out_size)
{
    const float* node = (const float*)d_in[0];
    const float* edge = (const float*)d_in[1];
    const float* Wq   = (const float*)d_in[2];
    const float* Wk   = (const float*)d_in[3];
    const float* Wv   = (const float*)d_in[4];
    const float* Wp   = (const float*)d_in[5];
    const float* bp   = (const float*)d_in[6];
    const float* ln1g = (const float*)d_in[7];
    const float* ln1b = (const float*)d_in[8];
    const float* W1   = (const float*)d_in[9];
    const float* b1   = (const float*)d_in[10];
    const float* W2   = (const float*)d_in[11];
    const float* b2   = (const float*)d_in[12];
    const float* ln2g = (const float*)d_in[13];
    const float* ln2b = (const float*)d_in[14];

    float *qkv, *qe, *logits, *mo, *x, *ffh, *wqkv, *part;
    cudaGetSymbolAddress((void**)&qkv,    g_qkv);
    cudaGetSymbolAddress((void**)&qe,     g_qe);
    cudaGetSymbolAddress((void**)&logits, g_logits);
    cudaGetSymbolAddress((void**)&mo,     g_mo);
    cudaGetSymbolAddress((void**)&x,      g_x);
    cudaGetSymbolAddress((void**)&ffh,    g_ffh);
    cudaGetSymbolAddress((void**)&wqkv,   g_wqkv);
    cudaGetSymbolAddress((void**)&part,   g_part);

    cudaFuncSetAttribute(edge_softmax_kernel,
                         cudaFuncAttributeMaxDynamicSharedMemorySize, EDGE_SMEM_BYTES);

    // 0) weight repack (k-major [256][1536])
    repack_wqkv<<<(D_*QKV_ + 255)/256, 256>>>(Wq, Wk, Wv, wqkv);

    // 1) fused QKV projection (unsplit; 384 CTAs): qkv = node @ wqkv
    mgemm<128,64,4,2><<<dim3(QKV_/64, R_/128, 1), 256>>>(
        node, wqkv, (const float*)0, qkv, D_,
        D_, 0, 0,
        QKV_, 1, 0, 0,
        QKV_, 0, 0, 1, 1, 0);

    // 2) qe[r][h*64+e] = q_h[r,:] @ WkE_h^T   (z = h; 256 CTAs; n-major B)
    mgemm<64,64,2,4><<<dim3(1, R_/64, H_), 256>>>(
        qkv, Wk + (long)D_*HS_, (const float*)0, qe, HS_,
        QKV_, 64, 0,
        1, HS_, (long)(D_+E_)*HS_, 0,
        (long)H_*E_, 64, 0, 1, 1, 0);

    // 3) QK^T logits (z = b*8+h; 2048 CTAs; n-major B = kn)
    mgemm<128,64,4,2><<<dim3(N_/64, N_/128, B_*H_), 256>>>(
        qkv, qkv + 512, (const float*)0, logits, HS_,
        QKV_, (long)N_*QKV_, 64,
        1, QKV_, (long)N_*QKV_, 64,
        N_, (long)H_*N_*N_, (long)N_*N_, H_, 1, 0);

    // 4) edge logits + softmax (streams 536 MB; in-place probs; 3 CTAs/SM)
    edge_softmax_kernel<<<R_, 256, EDGE_SMEM_BYTES>>>(edge, qe, logits);

    // 5) AV split-K4: part[ks] = attn[.., chunk] @ v[chunk]  (1024 CTAs; k-major B)
    mgemm<64,64,2,4><<<dim3(1, N_/64, B_*H_*4), 256>>>(
        logits, qkv + 1024, (const float*)0, part, N_/4,
        N_, (long)H_*N_*N_, (long)N_*N_,
        QKV_, 1, (long)N_*QKV_, 64,
        (long)H_*HS_, (long)N_*H_*HS_, 64, H_, 4, (long)R_*512);
    reduce_add<<<(R_*512/4 + 255)/256, 256>>>(part, mo, R_*512/4, 4, (long)R_*512/4);

    // 6) output projection split-K2: part[ks] = mo[..,ks] @ Wp[ks]  (256 CTAs)
    mgemm<64,64,2,4><<<dim3(D_/64, R_/64, 2), 256>>>(
        mo, Wp, (const float*)0, part, (H_*HS_)/2,
        (long)H_*HS_, 0, 0,
        D_, 1, 0, 0,
        D_, 0, 0, 1, 2, (long)R_*D_);

    // 7) x = LN1(node + part0 + part1 + bp)   (reduce fused into LN)
    ln_kernel<<<R_/8, 256>>>(node, part, 2, (long)R_*D_/4, bp, ln1g, ln1b, x);

    // 8) FFN hidden (unsplit; 256 CTAs): ffh = x @ W1  (b1+relu fused into step 9)
    mgemm<128,64,4,2><<<dim3(FF_/64, R_/128, 1), 256>>>(
        x, W1, (const float*)0, ffh, D_,
        D_, 0, 0,
        FF_, 1, 0, 0,
        FF_, 0, 0, 1, 1, 0);

    // 9) FFN out split-K4: part[ks] = relu(ffh+b1)[ks] @ W2[ks]  (512 CTAs)
    mgemm<64,64,2,4><<<dim3(D_/64, R_/64, 4), 256>>>(
        ffh, W2, b1, part, FF_/4,
        FF_, 0, 0,
        D_, 1, 0, 0,
        D_, 0, 0, 1, 4, (long)R_*D_);

    // 10) out = LN2(x + part0..3 + b2)   (reduce fused into LN)
    ln_kernel<<<R_/8, 256>>>(x, part, 4, (long)R_*D_/4, b2, ln2g, ln2b, (float*)d_out);
}